// round 12
// baseline (speedup 1.0000x reference)
#include <cuda_runtime.h>
#include <cuda_bf16.h>
#include <math.h>
#include <stdint.h>

// ---------------- problem constants ----------------
#define TT   2048
#define BBX  2
#define SS   1024
#define DD   2048
#define HH   16
#define KVH  8
#define HD   128
#define KVD  1024
#define FF_  8192
#define LL   4
#define VV   32000

typedef __nv_bfloat16 bf16;

#if defined(__CUDA_ARCH_FEAT_SM103_ALL) || defined(__CUDA_ARCH_FEAT_SM100_ALL) || defined(__CUDA_ARCH_FEAT_SM101_ALL)
#define HAS_TCGEN05 1
#else
#define HAS_TCGEN05 0
#endif

// epilogue modes
#define EP_F32   0
#define EP_SILU  1
#define EP_SPLIT 2
#define EP_QKV   3
// causal modes: 0 none; 1 = N-tile skip (scores); 2 = K-chunk limit per M-tile (PV)

// ---------------- scratch ----------------
__device__ __align__(256) float g_X  [TT * DD];
__device__ __align__(256) float g_V  [TT * KVD];
__device__ __align__(256) float g_SC [(size_t)BBX * HH * SS * SS];

__device__ __align__(256) bf16 g_XNh[TT * DD],  g_XNl[TT * DD];
__device__ __align__(256) bf16 g_Qh [TT * DD],  g_Ql [TT * DD];
__device__ __align__(256) bf16 g_Kh [TT * KVD], g_Kl [TT * KVD];
__device__ __align__(256) bf16 g_VTh[TT * KVD], g_VTl[TT * KVD];
__device__ __align__(256) bf16 g_Ph [(size_t)BBX * HH * SS * SS];
__device__ __align__(256) bf16 g_Pl [(size_t)BBX * HH * SS * SS];
__device__ __align__(256) bf16 g_AOh[TT * DD],  g_AOl[TT * DD];
__device__ __align__(256) bf16 g_Gh [(size_t)TT * FF_], g_Gl[(size_t)TT * FF_];

// per-layer weight buffers (no reuse across layers -> no WAR hazard vs side stream)
__device__ __align__(256) bf16 g_Wqkvh[LL][(size_t)4096 * DD],  g_Wqkvl[LL][(size_t)4096 * DD];
__device__ __align__(256) bf16 g_Woh  [LL][(size_t)DD * DD],    g_Wol  [LL][(size_t)DD * DD];
__device__ __align__(256) bf16 g_Wguh [LL][(size_t)16384 * DD], g_Wgul [LL][(size_t)16384 * DD];
__device__ __align__(256) bf16 g_Wdh  [LL][(size_t)DD * FF_],   g_Wdl  [LL][(size_t)DD * FF_];
__device__ __align__(256) bf16 g_Lmhh [(size_t)VV * DD],        g_Lmhl [(size_t)VV * DD];

// ---------------- helpers ----------------
__device__ __forceinline__ uint32_t s2u(const void* p) {
    uint32_t a;
    asm("{ .reg .u64 t; cvta.to.shared.u64 t, %1; cvt.u32.u64 %0, t; }" : "=r"(a) : "l"(p));
    return a;
}
__device__ __forceinline__ uint32_t elect1() {
    uint32_t r;
    asm volatile("{\n\t.reg .pred p;\n\telect.sync _|p, 0xFFFFFFFF;\n\tselp.b32 %0, 1, 0, p;\n\t}" : "=r"(r));
    return r;
}
__device__ __forceinline__ uint32_t lds32(uint32_t a) {
    uint32_t v;
    asm volatile("ld.shared.b32 %0, [%1];" : "=r"(v) : "r"(a));
    return v;
}
#define SWZ64(x) ((x) ^ (((x) >> 3) & 0x30))

#define CPA16(d, s) \
    asm volatile("cp.async.cg.shared.global [%0], [%1], 16;" :: "r"(d), "l"(__cvta_generic_to_global(s)))
#define CP_COMMIT()  asm volatile("cp.async.commit_group;" ::: "memory")
#define CP_WAIT1()   asm volatile("cp.async.wait_group 1;" ::: "memory")
#define CP_WAIT0()   asm volatile("cp.async.wait_group 0;" ::: "memory")

__device__ __forceinline__ void split1(float v, bf16& h, bf16& l) {
    h = __float2bfloat16(v);
    l = __float2bfloat16(v - __bfloat162float(h));
}
__device__ __forceinline__ uint32_t packsplit(float a, float b, uint32_t& lo) {
    bf16 ha = __float2bfloat16(a), hb = __float2bfloat16(b);
    bf16 la = __float2bfloat16(a - __bfloat162float(ha));
    bf16 lb = __float2bfloat16(b - __bfloat162float(hb));
    lo = (uint32_t)*(uint16_t*)&la | ((uint32_t)*(uint16_t*)&lb << 16);
    return (uint32_t)*(uint16_t*)&ha | ((uint32_t)*(uint16_t*)&hb << 16);
}
__device__ __forceinline__ void split_store8(bf16* dh, bf16* dl, float4 a, float4 b) {
    uint32_t l0, l1, l2, l3;
    uint32_t h0 = packsplit(a.x, a.y, l0);
    uint32_t h1 = packsplit(a.z, a.w, l1);
    uint32_t h2 = packsplit(b.x, b.y, l2);
    uint32_t h3 = packsplit(b.z, b.w, l3);
    *(uint4*)dh = make_uint4(h0, h1, h2, h3);
    *(uint4*)dl = make_uint4(l0, l1, l2, l3);
}
__device__ __forceinline__ void split_store32(bf16* dh, bf16* dl, const float* v) {
    uint32_t wh[16], wl[16];
#pragma unroll
    for (int q = 0; q < 16; q++) wh[q] = packsplit(v[2*q], v[2*q+1], wl[q]);
    uint4* H = (uint4*)dh; uint4* L = (uint4*)dl;
#pragma unroll
    for (int q = 0; q < 4; q++) {
        H[q] = make_uint4(wh[4*q], wh[4*q+1], wh[4*q+2], wh[4*q+3]);
        L[q] = make_uint4(wl[4*q], wl[4*q+1], wl[4*q+2], wl[4*q+3]);
    }
}
__device__ __forceinline__ void split_store16(bf16* dh, bf16* dl, const float* v) {
    uint32_t wh[8], wl[8];
#pragma unroll
    for (int q = 0; q < 8; q++) wh[q] = packsplit(v[2*q], v[2*q+1], wl[q]);
    uint4* H = (uint4*)dh; uint4* L = (uint4*)dl;
#pragma unroll
    for (int q = 0; q < 2; q++) {
        H[q] = make_uint4(wh[4*q], wh[4*q+1], wh[4*q+2], wh[4*q+3]);
        L[q] = make_uint4(wl[4*q], wl[4*q+1], wl[4*q+2], wl[4*q+3]);
    }
}
__device__ __forceinline__ void rope1(int pos, int i, float x1, float x2, float& o1, float& o2) {
    float freq = __expf(-(float)(2 * i) * (1.0f / 128.0f) * 9.210340371976184f);
    float sn, cs;
    sincosf((float)pos * freq, &sn, &cs);
    o1 = x1 * cs - x2 * sn;
    o2 = x1 * sn + x2 * cs;
}

#if HAS_TCGEN05
constexpr uint64_t DESCBASE64 =
    (uint64_t(4) << 61) | (uint64_t(1) << 46) | (uint64_t(32) << 32) | (uint64_t(1) << 16);
__device__ __forceinline__ uint64_t mk64(uint32_t a) {
    return DESCBASE64 | ((uint64_t)(a >> 4) & 0x3FFF);
}
__device__ __forceinline__ void mma_f16_ss(uint32_t d, uint64_t ad, uint64_t bd,
                                           uint32_t idesc, uint32_t en) {
    asm volatile(
        "{\n\t.reg .pred p;\n\tsetp.ne.u32 p, %4, 0;\n\t"
        "tcgen05.mma.cta_group::1.kind::f16 [%0], %1, %2, %3, {%5,%5,%5,%5}, p;\n\t}"
        :: "r"(d), "l"(ad), "l"(bd), "r"(idesc), "r"(en), "r"(0u) : "memory");
}
#define MBAR_INIT(a, c) \
    asm volatile("mbarrier.init.shared.b64 [%0], %1;" :: "r"(a), "r"(c) : "memory")
#define TC_COMMIT(a) \
    asm volatile("tcgen05.commit.cta_group::1.mbarrier::arrive::one.shared::cluster.b64 [%0];" :: "r"(a) : "memory")
#define TC_ALLOC(sa, n) \
    asm volatile("tcgen05.alloc.cta_group::1.sync.aligned.shared::cta.b32 [%0], %1;" :: "r"(sa), "r"(n) : "memory")
#define TC_DEALLOC(t, n) \
    asm volatile("tcgen05.dealloc.cta_group::1.sync.aligned.b32 %0, %1;" :: "r"(t), "r"(n))
#define TC_RELINQ() \
    asm volatile("tcgen05.relinquish_alloc_permit.cta_group::1.sync.aligned;")
#define TC_FENCE_AFTER()  asm volatile("tcgen05.fence::after_thread_sync;" ::: "memory")
#define TC_WAIT_LD()      asm volatile("tcgen05.wait::ld.sync.aligned;" ::: "memory")

__device__ __forceinline__ void mbar_wait(uint32_t addr, uint32_t parity) {
    asm volatile(
        "{\n\t.reg .pred P;\n\t"
        "WL_%=:\n\t"
        "mbarrier.try_wait.parity.acquire.cta.shared::cta.b64 P, [%0], %1, 0x989680;\n\t"
        "@P bra.uni WD_%=;\n\t"
        "bra.uni WL_%=;\n\t"
        "WD_%=:\n\t}"
        :: "r"(addr), "r"(parity) : "memory");
}

#define TC_LD_X32(r, a) \
    asm volatile( \
        "tcgen05.ld.sync.aligned.32x32b.x32.b32 " \
        "{%0, %1, %2, %3, %4, %5, %6, %7, %8, %9, %10, %11, %12, %13, %14, %15, " \
        " %16, %17, %18, %19, %20, %21, %22, %23, %24, %25, %26, %27, %28, %29, %30, %31}, [%32];" \
        : "=r"((r)[0]), "=r"((r)[1]), "=r"((r)[2]), "=r"((r)[3]), \
          "=r"((r)[4]), "=r"((r)[5]), "=r"((r)[6]), "=r"((r)[7]), \
          "=r"((r)[8]), "=r"((r)[9]), "=r"((r)[10]), "=r"((r)[11]), \
          "=r"((r)[12]), "=r"((r)[13]), "=r"((r)[14]), "=r"((r)[15]), \
          "=r"((r)[16]), "=r"((r)[17]), "=r"((r)[18]), "=r"((r)[19]), \
          "=r"((r)[20]), "=r"((r)[21]), "=r"((r)[22]), "=r"((r)[23]), \
          "=r"((r)[24]), "=r"((r)[25]), "=r"((r)[26]), "=r"((r)[27]), \
          "=r"((r)[28]), "=r"((r)[29]), "=r"((r)[30]), "=r"((r)[31]) \
        : "r"(a))
#endif  // HAS_TCGEN05

// ======= bf16x3 GEMM: out = (A @ B^T) variants, CTA tile 256 x NT, K-chunk 32 =======
// 512 threads: 16 warps; warp 0 issues MMA; all load; epilogue split 2x wider.
#define SM_A 1024
#define SM_B 99328   /* 1024 + 6*16384 */
template<int NT>
__global__ __launch_bounds__(512) void mma_gemm_kernel(
    const bf16* __restrict__ Ahi, const bf16* __restrict__ Alo,
    const bf16* __restrict__ Bhi, const bf16* __restrict__ Blo,
    float* __restrict__ Cf, bf16* __restrict__ Ch, bf16* __restrict__ Cl,
    bf16* __restrict__ Dh, bf16* __restrict__ Dl,
    const float* __restrict__ Res,
    int K, int lda, int ldb, int ldc,
    int Hdim, int hshiftB,
    long long sAb, long long sAh, long long sBb, long long sBh,
    long long sCb, long long sCh, float alpha, int causal, int mode)
{
    if (causal == 1 && (int)blockIdx.y * NT > (int)blockIdx.x * 256 + 255) return;
    extern __shared__ char smem[];
    uint32_t sb = s2u(smem);
    int tid = threadIdx.x, wid = tid >> 5, lane = tid & 31;
    int z = blockIdx.z;
    int bi = z / Hdim, hi = z - bi * Hdim;

    const bf16* Ah = Ahi + bi * sAb + hi * sAh + (long long)blockIdx.x * 256 * lda;
    const bf16* Al = Alo + bi * sAb + hi * sAh + (long long)blockIdx.x * 256 * lda;
    const bf16* Bh = Bhi + bi * sBb + (long long)(hi >> hshiftB) * sBh + (long long)blockIdx.y * NT * ldb;
    const bf16* Bl = Blo + bi * sBb + (long long)(hi >> hshiftB) * sBh + (long long)blockIdx.y * NT * ldb;
    long long cbase = bi * sCb + hi * sCh + (long long)blockIdx.x * 256 * ldc
                      + (long long)blockIdx.y * NT;

    int NC = K >> 5;
    if (causal == 2) {                      // PV: keys beyond the diagonal never needed
        int lim = ((int)blockIdx.x + 1) * 8;
        if (lim < NC) NC = lim;
    }
    constexpr int NTB = NT * 64;

    auto load_stage = [&](int s, int kc) {
        long long kof = (long long)kc * 32;
        for (int i = tid; i < 2048; i += 512) {
            int p = i >> 10, rem = i & 1023, r = rem >> 2, c = rem & 3;
            const bf16* src = (p ? Al : Ah) + (long long)r * lda + kof + c * 8;
            CPA16(sb + SM_A + (s * 2 + p) * 16384 + SWZ64(r * 64 + c * 16), src);
        }
        for (int i = tid; i < 2 * NT * 4; i += 512) {
            int p = i / (NT * 4), rem = i % (NT * 4), r = rem >> 2, c = rem & 3;
            const bf16* src = (p ? Bl : Bh) + (long long)r * ldb + kof + c * 8;
            CPA16(sb + SM_B + (s * 2 + p) * NTB + SWZ64(r * 64 + c * 16), src);
        }
        CP_COMMIT();
    };

#if HAS_TCGEN05
    if (tid == 0) { MBAR_INIT(sb + 8, 1); MBAR_INIT(sb + 16, 1); MBAR_INIT(sb + 24, 1); }
    if (wid == 0) TC_ALLOC(sb, 2 * NT);
    __syncthreads();
    uint32_t tb;
    asm volatile("ld.shared.b32 %0, [%1];" : "=r"(tb) : "r"(sb));

    constexpr uint32_t IDESC =
        (1u << 4) | (1u << 7) | (1u << 10) | ((uint32_t)(NT / 8) << 17) | (8u << 24);

    load_stage(0, 0);
    load_stage(1, 1);
    int wp[3] = {0, 0, 0};
#pragma unroll 1
    for (int c = 0; c < NC; c++) {
        int s = c % 3;
        if (c + 1 < NC) CP_WAIT1(); else CP_WAIT0();
        asm volatile("fence.proxy.async.shared::cta;" ::: "memory");
        __syncthreads();
        if (wid == 0 && elect1()) {
            uint32_t AbH = sb + SM_A + (s * 2 + 0) * 16384;
            uint32_t AbL = sb + SM_A + (s * 2 + 1) * 16384;
            uint64_t dBh = mk64(sb + SM_B + (s * 2 + 0) * NTB);
            uint64_t dBl = mk64(sb + SM_B + (s * 2 + 1) * NTB);
            uint32_t en0 = (c > 0);
#pragma unroll
            for (int m = 0; m < 2; m++) {
                uint64_t dAh = mk64(AbH + m * 8192);
                uint64_t dAl = mk64(AbL + m * 8192);
                uint32_t D = tb + m * NT;
                mma_f16_ss(D, dAh + 0, dBh + 0, IDESC, en0);
                mma_f16_ss(D, dAh + 2, dBh + 2, IDESC, 1u);
                mma_f16_ss(D, dAh + 0, dBl + 0, IDESC, 1u);
                mma_f16_ss(D, dAh + 2, dBl + 2, IDESC, 1u);
                mma_f16_ss(D, dAl + 0, dBh + 0, IDESC, 1u);
                mma_f16_ss(D, dAl + 2, dBh + 2, IDESC, 1u);
            }
            TC_COMMIT(sb + 8 + s * 8);
        }
        if (c + 2 < NC) {
            int s2 = (c + 2) % 3;
            if (c >= 1) { mbar_wait(sb + 8 + s2 * 8, wp[s2] & 1); wp[s2]++; }
            load_stage(s2, c + 2);
        }
    }
    {
        int sf = (NC - 1) % 3;
        mbar_wait(sb + 8 + sf * 8, wp[sf] & 1);
    }
    TC_FENCE_AFTER();

    {
        // 16 warps: m = (wid>>2)&1 selects M-half; cg = wid>>3 selects col-group.
        int m = (wid >> 2) & 1;
        int cg = wid >> 3;
        constexpr int CBW = NT / 64;       // col blocks per warp group
        int lrow = m * 128 + (wid & 3) * 32 + lane;
        int grow = blockIdx.x * 256 + lrow;
        if (mode == EP_F32) {
            long long rbase = cbase + (long long)lrow * ldc;
#pragma unroll 1
            for (int q = 0; q < CBW; q++) {
                int cb = cg * CBW + q;
                uint32_t r[32];
                TC_LD_X32(r, tb + m * NT + cb * 32);
                TC_WAIT_LD();
                long long base = rbase + cb * 32;
#pragma unroll
                for (int j = 0; j < 32; j += 4) {
                    float4 v;
                    v.x = __uint_as_float(r[j + 0]) * alpha;
                    v.y = __uint_as_float(r[j + 1]) * alpha;
                    v.z = __uint_as_float(r[j + 2]) * alpha;
                    v.w = __uint_as_float(r[j + 3]) * alpha;
                    if (Res) {
                        float4 q2 = *(const float4*)(Res + base + j);
                        v.x += q2.x; v.y += q2.y; v.z += q2.z; v.w += q2.w;
                    }
                    *(float4*)(Cf + base + j) = v;
                }
            }
        } else if (mode == EP_SPLIT) {
            long long rbase = cbase + (long long)lrow * ldc;
#pragma unroll 1
            for (int q = 0; q < CBW; q++) {
                int cb = cg * CBW + q;
                uint32_t r[32];
                TC_LD_X32(r, tb + m * NT + cb * 32);
                TC_WAIT_LD();
                float v[32];
#pragma unroll
                for (int j = 0; j < 32; j++) v[j] = __uint_as_float(r[j]);
                split_store32(Ch + rbase + cb * 32, Cl + rbase + cb * 32, v);
            }
        } else if (mode == EP_SILU) {
            long long rbase = (long long)grow * (ldc >> 1) + (long long)blockIdx.y * (NT / 2);
#pragma unroll 1
            for (int q = 0; q < CBW; q++) {
                int cb = cg * CBW + q;
                uint32_t r[32];
                TC_LD_X32(r, tb + m * NT + cb * 32);
                TC_WAIT_LD();
                float v[16];
#pragma unroll
                for (int q2 = 0; q2 < 16; q2++) {
                    float g = __uint_as_float(r[2 * q2]);
                    float u = __uint_as_float(r[2 * q2 + 1]);
                    v[q2] = g * u / (1.0f + __expf(-g));
                }
                split_store16(Ch + rbase + cb * 16, Cl + rbase + cb * 16, v);
            }
        } else {  // EP_QKV (NT == 256)
            int y = blockIdx.y;
            if (y >= 12) {
                long long vb = (long long)grow * 1024 + (y - 12) * 256;
#pragma unroll 1
                for (int q = 0; q < 4; q++) {
                    int cb = cg * 4 + q;
                    uint32_t r[32];
                    TC_LD_X32(r, tb + m * NT + cb * 32);
                    TC_WAIT_LD();
#pragma unroll
                    for (int j = 0; j < 32; j += 4) {
                        float4 v;
                        v.x = __uint_as_float(r[j + 0]);
                        v.y = __uint_as_float(r[j + 1]);
                        v.z = __uint_as_float(r[j + 2]);
                        v.w = __uint_as_float(r[j + 3]);
                        *(float4*)(Cf + vb + cb * 32 + j) = v;
                    }
                }
            } else {
                int pos = grow & (SS - 1);
                const int pps[4] = {0, 1, 4, 5};
#pragma unroll 1
                for (int t = cg * 2; t < cg * 2 + 2; t++) {
                    int pp = pps[t];
                    uint32_t r1[32], r2[32];
                    TC_LD_X32(r1, tb + m * NT + pp * 32);
                    TC_LD_X32(r2, tb + m * NT + (pp + 2) * 32);
                    TC_WAIT_LD();
                    int ibase = (pp & 1) * 32;
                    int col0 = y * 256 + ((pp >> 2) << 7);
                    float v1[32], v2[32];
#pragma unroll
                    for (int j = 0; j < 32; j++) {
                        rope1(pos, ibase + j,
                              __uint_as_float(r1[j]), __uint_as_float(r2[j]),
                              v1[j], v2[j]);
                    }
                    if (y < 8) {
                        long long ob = (long long)grow * 2048 + col0 + ibase;
                        split_store32(Ch + ob, Cl + ob, v1);
                        split_store32(Ch + ob + 64, Cl + ob + 64, v2);
                    } else {
                        long long ob = (long long)grow * 1024 + (col0 - 2048) + ibase;
                        split_store32(Dh + ob, Dl + ob, v1);
                        split_store32(Dh + ob + 64, Dl + ob + 64, v2);
                    }
                }
            }
        }
    }
    __syncthreads();
    if (wid == 0) { TC_RELINQ(); TC_DEALLOC(tb, 2 * NT); }

#else
    // ------- mma.sync fallback (compute_103-legal; not selected on sm_103a) -------
    int g = lane >> 2, tg = lane & 3;
    int w8 = wid & 7;
#pragma unroll 1
    for (int nh = 0; nh < NT / 128; nh++) {
        float acc[2][16][4];
#pragma unroll
        for (int g2 = 0; g2 < 2; g2++)
#pragma unroll
            for (int i = 0; i < 16; i++)
#pragma unroll
                for (int j = 0; j < 4; j++) acc[g2][i][j] = 0.f;
#pragma unroll 1
        for (int c = 0; c < NC; c++) {
            __syncthreads();
            load_stage(0, c);
            CP_WAIT0();
            __syncthreads();
            if (wid < 8) {
#pragma unroll 1
                for (int pass = 0; pass < 3; pass++) {
                    int pa = (pass == 2) ? 1 : 0;
                    int pb = (pass == 1) ? 1 : 0;
                    uint32_t At = sb + SM_A + pa * 16384;
                    uint32_t Bt = sb + SM_B + pb * NTB;
#pragma unroll 1
                    for (int g2 = 0; g2 < 2; g2++) {
                        int R = (w8 * 2 + g2) * 16;
#pragma unroll
                        for (int ks = 0; ks < 2; ks++) {
                            int k0 = ks * 16;
                            uint32_t a0 = lds32(At + SWZ64((R + g) * 64 + (k0 + tg * 2) * 2));
                            uint32_t a1 = lds32(At + SWZ64((R + g + 8) * 64 + (k0 + tg * 2) * 2));
                            uint32_t a2 = lds32(At + SWZ64((R + g) * 64 + (k0 + 8 + tg * 2) * 2));
                            uint32_t a3 = lds32(At + SWZ64((R + g + 8) * 64 + (k0 + 8 + tg * 2) * 2));
#pragma unroll
                            for (int nt = 0; nt < 16; nt++) {
                                int br = nh * 128 + nt * 8 + g;
                                uint32_t b0 = lds32(Bt + SWZ64(br * 64 + (k0 + tg * 2) * 2));
                                uint32_t b1 = lds32(Bt + SWZ64(br * 64 + (k0 + 8 + tg * 2) * 2));
                                asm volatile(
                                    "mma.sync.aligned.m16n8k16.row.col.f32.bf16.bf16.f32 "
                                    "{%0,%1,%2,%3}, {%4,%5,%6,%7}, {%8,%9}, {%0,%1,%2,%3};"
                                    : "+f"(acc[g2][nt][0]), "+f"(acc[g2][nt][1]),
                                      "+f"(acc[g2][nt][2]), "+f"(acc[g2][nt][3])
                                    : "r"(a0), "r"(a1), "r"(a2), "r"(a3), "r"(b0), "r"(b1));
                            }
                        }
                    }
                }
            }
        }
        if (wid < 8) {
#pragma unroll 1
            for (int g2 = 0; g2 < 2; g2++) {
                int R = (w8 * 2 + g2) * 16;
#pragma unroll 1
                for (int rh = 0; rh < 2; rh++) {
                    int lrow = R + g + rh * 8;
                    int grow = blockIdx.x * 256 + lrow;
                    if (mode == EP_F32 || (mode == EP_QKV && blockIdx.y >= 12)) {
#pragma unroll
                        for (int nt = 0; nt < 16; nt++) {
                            int col = nh * 128 + nt * 8 + tg * 2;
                            long long o = (mode == EP_F32)
                                ? cbase + (long long)lrow * ldc + col
                                : (long long)grow * 1024 + (blockIdx.y - 12) * 256 + col;
                            float a0 = acc[g2][nt][rh * 2] * alpha;
                            float a1 = acc[g2][nt][rh * 2 + 1] * alpha;
                            if (mode == EP_F32 && Res) { a0 += Res[o]; a1 += Res[o + 1]; }
                            Cf[o] = a0; Cf[o + 1] = a1;
                        }
                    } else if (mode == EP_SPLIT) {
#pragma unroll
                        for (int nt = 0; nt < 16; nt++) {
                            int col = nh * 128 + nt * 8 + tg * 2;
                            long long o = cbase + (long long)lrow * ldc + col;
                            bf16 h, l;
                            split1(acc[g2][nt][rh * 2], h, l);     Ch[o] = h;     Cl[o] = l;
                            split1(acc[g2][nt][rh * 2 + 1], h, l); Ch[o + 1] = h; Cl[o + 1] = l;
                        }
                    } else if (mode == EP_SILU) {
#pragma unroll
                        for (int nt = 0; nt < 16; nt++) {
                            int col = blockIdx.y * NT + nh * 128 + nt * 8 + tg * 2;
                            float gg = acc[g2][nt][rh * 2], uu = acc[g2][nt][rh * 2 + 1];
                            float s = gg * uu / (1.0f + __expf(-gg));
                            long long o = (long long)grow * (ldc >> 1) + col / 2;
                            bf16 h, l; split1(s, h, l);
                            Ch[o] = h; Cl[o] = l;
                        }
                    } else {
                        int pos = grow & (SS - 1);
#pragma unroll
                        for (int nt = 0; nt < 8; nt++) {
#pragma unroll
                            for (int k = 0; k < 2; k++) {
                                int i = nt * 8 + tg * 2 + k;
                                float x1 = acc[g2][nt][rh * 2 + k];
                                float x2 = acc[g2][nt + 8][rh * 2 + k];
                                float o1, o2;
                                rope1(pos, i, x1, x2, o1, o2);
                                int col0 = blockIdx.y * 256 + nh * 128;
                                bf16 h, l;
                                if (blockIdx.y < 8) {
                                    long long ob = (long long)grow * 2048 + col0 + i;
                                    split1(o1, h, l); Ch[ob] = h;      Cl[ob] = l;
                                    split1(o2, h, l); Ch[ob + 64] = h; Cl[ob + 64] = l;
                                } else {
                                    long long ob = (long long)grow * 1024 + (col0 - 2048) + i;
                                    split1(o1, h, l); Dh[ob] = h;      Dl[ob] = l;
                                    split1(o2, h, l); Dh[ob + 64] = h; Dl[ob + 64] = l;
                                }
                            }
                        }
                    }
                }
            }
        }
    }
#endif
}

// ================= elementwise kernels =================
__global__ void embed_kernel(const int* __restrict__ ids, const float* __restrict__ embed,
                             float* __restrict__ X) {
    int t = blockIdx.x;
    int id = ids[t];
    const float4* src = (const float4*)(embed + (long long)id * DD);
    float4* dst = (float4*)(X + (long long)t * DD);
    for (int i = threadIdx.x; i < DD / 4; i += blockDim.x) dst[i] = src[i];
}

__global__ void rmsnorm_split_kernel(const float* __restrict__ X, const float* __restrict__ w,
                                     bf16* __restrict__ oh, bf16* __restrict__ ol) {
    int t = blockIdx.x;
    const float* x = X + (long long)t * DD;
    float ss = 0.f;
    for (int i = threadIdx.x; i < DD; i += 256) { float v = x[i]; ss += v * v; }
    __shared__ float red[256];
    red[threadIdx.x] = ss;
    __syncthreads();
    for (int s = 128; s > 0; s >>= 1) {
        if (threadIdx.x < s) red[threadIdx.x] += red[threadIdx.x + s];
        __syncthreads();
    }
    float scale = rsqrtf(red[0] * (1.0f / DD) + 1e-6f);
    for (int i = threadIdx.x; i < DD; i += 256) {
        float v = x[i] * scale * w[i];
        bf16 h, l; split1(v, h, l);
        oh[(long long)t * DD + i] = h;
        ol[(long long)t * DD + i] = l;
    }
}

__global__ void qkvsplit_kernel(const float* __restrict__ wq, const float* __restrict__ wk,
                                const float* __restrict__ wv,
                                bf16* __restrict__ oh, bf16* __restrict__ ol) {
    long long off = ((long long)blockIdx.x * blockDim.x + threadIdx.x) * 8;
    if (off >= (long long)4096 * DD) return;
    const float* src;
    long long so;
    if (off < (long long)2048 * DD)      { src = wq; so = off; }
    else if (off < (long long)3072 * DD) { src = wk; so = off - (long long)2048 * DD; }
    else                                 { src = wv; so = off - (long long)3072 * DD; }
    float4 a = *(const float4*)(src + so);
    float4 b = *(const float4*)(src + so + 4);
    split_store8(oh + off, ol + off, a, b);
}

__global__ void gusplit_kernel(const float* __restrict__ wg, const float* __restrict__ wu,
                               bf16* __restrict__ oh, bf16* __restrict__ ol) {
    long long off = ((long long)blockIdx.x * blockDim.x + threadIdx.x) * 8;
    if (off >= (long long)16384 * DD) return;
    int orow = (int)(off >> 11);
    int col = (int)(off & 2047);
    int j = orow >> 1;
    const float* src = (orow & 1) ? wu : wg;
    long long so = (long long)j * DD + col;
    float4 a = *(const float4*)(src + so);
    float4 b = *(const float4*)(src + so + 4);
    split_store8(oh + off, ol + off, a, b);
}

__global__ void flat8split_kernel(const float* __restrict__ in,
                                  bf16* __restrict__ oh, bf16* __restrict__ ol, long long n) {
    long long off = ((long long)blockIdx.x * blockDim.x + threadIdx.x) * 8;
    if (off >= n) return;
    float4 a = *(const float4*)(in + off);
    float4 b = *(const float4*)(in + off + 4);
    split_store8(oh + off, ol + off, a, b);
}

__global__ void vtrans_kernel(const float* __restrict__ Vf,
                              bf16* __restrict__ oh, bf16* __restrict__ ol) {
    __shared__ float tile[32][33];
    int tb = blockIdx.x * 32;
    int cb = blockIdx.y * 32;
    int tx = threadIdx.x, ty = threadIdx.y;
    for (int k = ty; k < 32; k += 8)
        tile[k][tx] = Vf[(long long)(tb + k) * KVD + cb + tx];
    __syncthreads();
    for (int k = ty; k < 32; k += 8) {
        int ch = cb + k;
        int t = tb + tx;
        int b = t >> 10, s = t & 1023;
        bf16 h, l; split1(tile[tx][k], h, l);
        long long o = ((long long)(b * 1024 + ch)) * 1024 + s;
        oh[o] = h; ol[o] = l;
    }
}

__global__ void softmax_kernel(const float* __restrict__ SC,
                               bf16* __restrict__ Ph, bf16* __restrict__ Pl) {
    __shared__ float red[256];
    __shared__ float ex[SS];
    long long r = blockIdx.x;
    int q = (int)(r & (SS - 1));
    int kend = ((q >> 8) + 1) << 8;
    const float* row = SC + r * SS;
    int tid = threadIdx.x;
    float sum = 0.f;
    for (int k = tid; k < kend; k += 256) {
        float e = (k <= q) ? __expf(row[k]) : 0.f;
        ex[k] = e;
        sum += e;
    }
    red[tid] = sum; __syncthreads();
    for (int s = 128; s > 0; s >>= 1) {
        if (tid < s) red[tid] += red[tid + s];
        __syncthreads();
    }
    float inv = 1.0f / red[0];
    bf16* ph = Ph + r * SS;
    bf16* pl = Pl + r * SS;
    for (int k = tid * 2; k < kend; k += 512) {
        uint32_t lo;
        uint32_t hi = packsplit(ex[k] * inv, ex[k + 1] * inv, lo);
        *(uint32_t*)(ph + k) = hi;
        *(uint32_t*)(pl + k) = lo;
    }
}

// ================= host =================
template<int NT>
static void launch_gemm(dim3 grid,
                        const bf16* Ah, const bf16* Al, const bf16* Bh, const bf16* Bl,
                        float* Cf, bf16* Ch, bf16* Cl, bf16* Dh, bf16* Dl,
                        const float* Res,
                        int K, int lda, int ldb, int ldc,
                        int Hdim, int hshift,
                        long long sAb, long long sAh, long long sBb, long long sBh,
                        long long sCb, long long sCh, float alpha, int causal, int mode) {
    constexpr int SMEM = 99328 + 6 * NT * 64;
    cudaFuncSetAttribute(mma_gemm_kernel<NT>, cudaFuncAttributeMaxDynamicSharedMemorySize, SMEM);
    mma_gemm_kernel<NT><<<grid, 512, SMEM>>>(Ah, Al, Bh, Bl, Cf, Ch, Cl, Dh, Dl, Res,
                                             K, lda, ldb, ldc, Hdim, hshift,
                                             sAb, sAh, sBb, sBh, sCb, sCh,
                                             alpha, causal, mode);
}

extern "C" void kernel_launch(void* const* d_in, const int* in_sizes, int n_in,
                              void* d_out, int out_size) {
    const int*   ids   = (const int*)d_in[0];
    const float* embed = (const float*)d_in[3];
    const float* ln1   = (const float*)d_in[4];
    const float* wq    = (const float*)d_in[5];
    const float* wk    = (const float*)d_in[6];
    const float* wv    = (const float*)d_in[7];
    const float* wo    = (const float*)d_in[8];
    const float* ln2   = (const float*)d_in[9];
    const float* wg    = (const float*)d_in[10];
    const float* wu    = (const float*)d_in[11];
    const float* wd    = (const float*)d_in[12];
    const float* nrm   = (const float*)d_in[13];
    const float* lmh   = (const float*)d_in[14];
    float* out = (float*)d_out;

    float *X, *Vf, *SC;
    bf16 *XNh, *XNl, *Qh, *Ql, *Kh, *Kl, *VTh, *VTl, *Ph, *Pl, *AOh, *AOl, *Gh, *Gl;
    bf16 *Lmhh, *Lmhl;
    bf16 *Wqkvh[LL], *Wqkvl[LL], *Woh[LL], *Wol[LL], *Wguh[LL], *Wgul[LL], *Wdh[LL], *Wdl[LL];
    cudaGetSymbolAddress((void**)&X, g_X);
    cudaGetSymbolAddress((void**)&Vf, g_V);
    cudaGetSymbolAddress((void**)&SC, g_SC);
    cudaGetSymbolAddress((void**)&XNh, g_XNh);   cudaGetSymbolAddress((void**)&XNl, g_XNl);
    cudaGetSymbolAddress((void**)&Qh, g_Qh);     cudaGetSymbolAddress((void**)&Ql, g_Ql);
    cudaGetSymbolAddress((void**)&Kh, g_Kh);     cudaGetSymbolAddress((void**)&Kl, g_Kl);
    cudaGetSymbolAddress((void**)&VTh, g_VTh);   cudaGetSymbolAddress((void**)&VTl, g_VTl);
    cudaGetSymbolAddress((void**)&Ph, g_Ph);     cudaGetSymbolAddress((void**)&Pl, g_Pl);
    cudaGetSymbolAddress((void**)&AOh, g_AOh);   cudaGetSymbolAddress((void**)&AOl, g_AOl);
    cudaGetSymbolAddress((void**)&Gh, g_Gh);     cudaGetSymbolAddress((void**)&Gl, g_Gl);
    cudaGetSymbolAddress((void**)&Lmhh, g_Lmhh); cudaGetSymbolAddress((void**)&Lmhl, g_Lmhl);
    {
        bf16 *p;
        cudaGetSymbolAddress((void**)&p, g_Wqkvh);
        for (int l = 0; l < LL; l++) Wqkvh[l] = p + (size_t)l * 4096 * DD;
        cudaGetSymbolAddress((void**)&p, g_Wqkvl);
        for (int l = 0; l < LL; l++) Wqkvl[l] = p + (size_t)l * 4096 * DD;
        cudaGetSymbolAddress((void**)&p, g_Woh);
        for (int l = 0; l < LL; l++) Woh[l] = p + (size_t)l * DD * DD;
        cudaGetSymbolAddress((void**)&p, g_Wol);
        for (int l = 0; l < LL; l++) Wol[l] = p + (size_t)l * DD * DD;
        cudaGetSymbolAddress((void**)&p, g_Wguh);
        for (int l = 0; l < LL; l++) Wguh[l] = p + (size_t)l * 16384 * DD;
        cudaGetSymbolAddress((void**)&p, g_Wgul);
        for (int l = 0; l < LL; l++) Wgul[l] = p + (size_t)l * 16384 * DD;
        cudaGetSymbolAddress((void**)&p, g_Wdh);
        for (int l = 0; l < LL; l++) Wdh[l] = p + (size_t)l * DD * FF_;
        cudaGetSymbolAddress((void**)&p, g_Wdl);
        for (int l = 0; l < LL; l++) Wdl[l] = p + (size_t)l * DD * FF_;
    }

    const float scale = 0.08838834764831845f;  // 1/sqrt(128)

    static cudaStream_t sSide = nullptr;
    static cudaEvent_t evRoot = nullptr;
    static cudaEvent_t evSplit[LL * 4 + 1];
    if (sSide == nullptr) {
        cudaStreamCreateWithFlags(&sSide, cudaStreamNonBlocking);
        cudaEventCreateWithFlags(&evRoot, cudaEventDisableTiming);
        for (int i = 0; i < LL * 4 + 1; i++)
            cudaEventCreateWithFlags(&evSplit[i], cudaEventDisableTiming);
    }

    // fork: all weight splits run on the side stream (depend only on inputs)
    cudaEventRecord(evRoot, 0);
    cudaStreamWaitEvent(sSide, evRoot, 0);
    for (int l = 0; l < LL; l++) {
        qkvsplit_kernel<<<4096, 256, 0, sSide>>>(
            wq + (long long)l * DD * DD, wk + (long long)l * KVD * DD,
            wv + (long long)l * KVD * DD, Wqkvh[l], Wqkvl[l]);
        cudaEventRecord(evSplit[l * 4 + 0], sSide);
        flat8split_kernel<<<2048, 256, 0, sSide>>>(
            wo + (long long)l * DD * DD, Woh[l], Wol[l], (long long)DD * DD);
        cudaEventRecord(evSplit[l * 4 + 1], sSide);
        gusplit_kernel<<<16384, 256, 0, sSide>>>(
            wg + (long long)l * FF_ * DD, wu + (long long)l * FF_ * DD, Wguh[l], Wgul[l]);
        cudaEventRecord(evSplit[l * 4 + 2], sSide);
        flat8split_kernel<<<8192, 256, 0, sSide>>>(
            wd + (long long)l * DD * FF_, Wdh[l], Wdl[l], (long long)DD * FF_);
        cudaEventRecord(evSplit[l * 4 + 3], sSide);
    }
    flat8split_kernel<<<32000, 256, 0, sSide>>>(lmh, Lmhh, Lmhl, (long long)VV * DD);
    cudaEventRecord(evSplit[LL * 4], sSide);

    // ---- main stream ----
    embed_kernel<<<TT, 256>>>(ids, embed, X);

    for (int l = 0; l < LL; l++) {
        rmsnorm_split_kernel<<<TT, 256>>>(X, ln1 + l * DD, XNh, XNl);

        cudaStreamWaitEvent(0, evSplit[l * 4 + 0], 0);
        launch_gemm<256>(dim3(8, 16, 1), XNh, XNl, Wqkvh[l], Wqkvl[l],
                         Vf, Qh, Ql, Kh, Kl, nullptr,
                         DD, DD, DD, 4096, 1, 0, 0, 0, 0, 0, 0, 0, 1.0f, 0, EP_QKV);

        vtrans_kernel<<<dim3(TT / 32, KVD / 32), dim3(32, 8)>>>(Vf, VTh, VTl);

        launch_gemm<256>(dim3(4, 4, 32), Qh, Ql, Kh, Kl,
                         SC, nullptr, nullptr, nullptr, nullptr, nullptr,
                         HD, DD, KVD, SS, HH, 1,
                         (long long)SS * DD, (long long)HD,
                         (long long)SS * KVD, (long long)HD,
                         (long long)HH * SS * SS, (long long)SS * SS, scale, 1, EP_F32);

        softmax_kernel<<<BBX * HH * SS, 256>>>(SC, Ph, Pl);

        launch_gemm<128>(dim3(4, 1, 32), Ph, Pl, VTh, VTl,
                         nullptr, AOh, AOl, nullptr, nullptr, nullptr,
                         SS, SS, SS, DD, HH, 1,
                         (long long)HH * SS * SS, (long long)SS * SS,
                         (long long)KVH * HD * SS, (long long)HD * SS,
                         (long long)SS * DD, (long long)HD, 1.0f, 2, EP_SPLIT);

        cudaStreamWaitEvent(0, evSplit[l * 4 + 1], 0);
        launch_gemm<128>(dim3(8, 16, 1), AOh, AOl, Woh[l], Wol[l],
                         X, nullptr, nullptr, nullptr, nullptr, X,
                         DD, DD, DD, DD, 1, 0, 0, 0, 0, 0, 0, 0, 1.0f, 0, EP_F32);

        rmsnorm_split_kernel<<<TT, 256>>>(X, ln2 + l * DD, XNh, XNl);

        cudaStreamWaitEvent(0, evSplit[l * 4 + 2], 0);
        launch_gemm<256>(dim3(8, 64, 1), XNh, XNl, Wguh[l], Wgul[l],
                         nullptr, Gh, Gl, nullptr, nullptr, nullptr,
                         DD, DD, DD, 16384, 1, 0, 0, 0, 0, 0, 0, 0, 1.0f, 0, EP_SILU);

        cudaStreamWaitEvent(0, evSplit[l * 4 + 3], 0);
        launch_gemm<128>(dim3(8, 16, 1), Gh, Gl, Wdh[l], Wdl[l],
                         X, nullptr, nullptr, nullptr, nullptr, X,
                         FF_, FF_, FF_, DD, 1, 0, 0, 0, 0, 0, 0, 0, 1.0f, 0, EP_F32);
    }

    rmsnorm_split_kernel<<<TT, 256>>>(X, nrm, XNh, XNl);
    cudaStreamWaitEvent(0, evSplit[LL * 4], 0);
    launch_gemm<256>(dim3(8, 125, 1), XNh, XNl, Lmhh, Lmhl,
                     out, nullptr, nullptr, nullptr, nullptr, nullptr,
                     DD, DD, DD, VV, 1, 0, 0, 0, 0, 0, 0, 0, 1.0f, 0, EP_F32);
}

// round 14
// speedup vs baseline: 1.4973x; 1.4973x over previous
#include <cuda_runtime.h>
#include <cuda_bf16.h>
#include <math.h>
#include <stdint.h>

// ---------------- problem constants ----------------
#define TT   2048
#define BBX  2
#define SS   1024
#define DD   2048
#define HH   16
#define KVH  8
#define HD   128
#define KVD  1024
#define FF_  8192
#define LL   4
#define VV   32000

typedef __nv_bfloat16 bf16;

#if defined(__CUDA_ARCH_FEAT_SM103_ALL) || defined(__CUDA_ARCH_FEAT_SM100_ALL) || defined(__CUDA_ARCH_FEAT_SM101_ALL)
#define HAS_TCGEN05 1
#else
#define HAS_TCGEN05 0
#endif

// epilogue modes
#define EP_F32   0
#define EP_SILU  1
#define EP_SPLIT 2
#define EP_QKV   3
// causal modes: 0 none; 1 = N-tile skip (scores); 2 = K-chunk limit per M-tile (PV)

// ---------------- scratch ----------------
__device__ __align__(256) float g_X  [TT * DD];
__device__ __align__(256) float g_SC [(size_t)BBX * HH * SS * SS];

__device__ __align__(256) bf16 g_XNh[TT * DD],  g_XNl[TT * DD];
__device__ __align__(256) bf16 g_Qh [TT * DD],  g_Ql [TT * DD];
__device__ __align__(256) bf16 g_Kh [TT * KVD], g_Kl [TT * KVD];
__device__ __align__(256) bf16 g_VTh[TT * KVD], g_VTl[TT * KVD];
__device__ __align__(256) bf16 g_Ph [(size_t)BBX * HH * SS * SS];
__device__ __align__(256) bf16 g_Pl [(size_t)BBX * HH * SS * SS];
__device__ __align__(256) bf16 g_AOh[TT * DD],  g_AOl[TT * DD];
__device__ __align__(256) bf16 g_Gh [(size_t)TT * FF_], g_Gl[(size_t)TT * FF_];

// per-layer weight buffers (no reuse across layers -> no WAR hazard vs side stream)
__device__ __align__(256) bf16 g_Wqkvh[LL][(size_t)4096 * DD],  g_Wqkvl[LL][(size_t)4096 * DD];
__device__ __align__(256) bf16 g_Woh  [LL][(size_t)DD * DD],    g_Wol  [LL][(size_t)DD * DD];
__device__ __align__(256) bf16 g_Wguh [LL][(size_t)16384 * DD], g_Wgul [LL][(size_t)16384 * DD];
__device__ __align__(256) bf16 g_Wdh  [LL][(size_t)DD * FF_],   g_Wdl  [LL][(size_t)DD * FF_];
__device__ __align__(256) bf16 g_Lmhh [(size_t)VV * DD],        g_Lmhl [(size_t)VV * DD];

// ---------------- helpers ----------------
__device__ __forceinline__ uint32_t s2u(const void* p) {
    uint32_t a;
    asm("{ .reg .u64 t; cvta.to.shared.u64 t, %1; cvt.u32.u64 %0, t; }" : "=r"(a) : "l"(p));
    return a;
}
__device__ __forceinline__ uint32_t elect1() {
    uint32_t r;
    asm volatile("{\n\t.reg .pred p;\n\telect.sync _|p, 0xFFFFFFFF;\n\tselp.b32 %0, 1, 0, p;\n\t}" : "=r"(r));
    return r;
}
__device__ __forceinline__ uint32_t lds32(uint32_t a) {
    uint32_t v;
    asm volatile("ld.shared.b32 %0, [%1];" : "=r"(v) : "r"(a));
    return v;
}
#define SWZ64(x) ((x) ^ (((x) >> 3) & 0x30))

#define CPA16(d, s) \
    asm volatile("cp.async.cg.shared.global [%0], [%1], 16;" :: "r"(d), "l"(__cvta_generic_to_global(s)))
#define CP_COMMIT()  asm volatile("cp.async.commit_group;" ::: "memory")
#define CP_WAIT1()   asm volatile("cp.async.wait_group 1;" ::: "memory")
#define CP_WAIT0()   asm volatile("cp.async.wait_group 0;" ::: "memory")

__device__ __forceinline__ void split1(float v, bf16& h, bf16& l) {
    h = __float2bfloat16(v);
    l = __float2bfloat16(v - __bfloat162float(h));
}
__device__ __forceinline__ uint32_t packsplit(float a, float b, uint32_t& lo) {
    bf16 ha = __float2bfloat16(a), hb = __float2bfloat16(b);
    bf16 la = __float2bfloat16(a - __bfloat162float(ha));
    bf16 lb = __float2bfloat16(b - __bfloat162float(hb));
    lo = (uint32_t)*(uint16_t*)&la | ((uint32_t)*(uint16_t*)&lb << 16);
    return (uint32_t)*(uint16_t*)&ha | ((uint32_t)*(uint16_t*)&hb << 16);
}
__device__ __forceinline__ void split_store8(bf16* dh, bf16* dl, float4 a, float4 b) {
    uint32_t l0, l1, l2, l3;
    uint32_t h0 = packsplit(a.x, a.y, l0);
    uint32_t h1 = packsplit(a.z, a.w, l1);
    uint32_t h2 = packsplit(b.x, b.y, l2);
    uint32_t h3 = packsplit(b.z, b.w, l3);
    *(uint4*)dh = make_uint4(h0, h1, h2, h3);
    *(uint4*)dl = make_uint4(l0, l1, l2, l3);
}
__device__ __forceinline__ void split_store32(bf16* dh, bf16* dl, const float* v) {
    uint32_t wh[16], wl[16];
#pragma unroll
    for (int q = 0; q < 16; q++) wh[q] = packsplit(v[2*q], v[2*q+1], wl[q]);
    uint4* H = (uint4*)dh; uint4* L = (uint4*)dl;
#pragma unroll
    for (int q = 0; q < 4; q++) {
        H[q] = make_uint4(wh[4*q], wh[4*q+1], wh[4*q+2], wh[4*q+3]);
        L[q] = make_uint4(wl[4*q], wl[4*q+1], wl[4*q+2], wl[4*q+3]);
    }
}
__device__ __forceinline__ void split_store16(bf16* dh, bf16* dl, const float* v) {
    uint32_t wh[8], wl[8];
#pragma unroll
    for (int q = 0; q < 8; q++) wh[q] = packsplit(v[2*q], v[2*q+1], wl[q]);
    uint4* H = (uint4*)dh; uint4* L = (uint4*)dl;
#pragma unroll
    for (int q = 0; q < 2; q++) {
        H[q] = make_uint4(wh[4*q], wh[4*q+1], wh[4*q+2], wh[4*q+3]);
        L[q] = make_uint4(wl[4*q], wl[4*q+1], wl[4*q+2], wl[4*q+3]);
    }
}
__device__ __forceinline__ void rope1(int pos, int i, float x1, float x2, float& o1, float& o2) {
    float freq = __expf(-(float)(2 * i) * (1.0f / 128.0f) * 9.210340371976184f);
    float sn, cs;
    sincosf((float)pos * freq, &sn, &cs);
    o1 = x1 * cs - x2 * sn;
    o2 = x1 * sn + x2 * cs;
}

#if HAS_TCGEN05
constexpr uint64_t DESCBASE64 =
    (uint64_t(4) << 61) | (uint64_t(1) << 46) | (uint64_t(32) << 32) | (uint64_t(1) << 16);
__device__ __forceinline__ uint64_t mk64(uint32_t a) {
    return DESCBASE64 | ((uint64_t)(a >> 4) & 0x3FFF);
}
__device__ __forceinline__ void mma_f16_ss(uint32_t d, uint64_t ad, uint64_t bd,
                                           uint32_t idesc, uint32_t en) {
    asm volatile(
        "{\n\t.reg .pred p;\n\tsetp.ne.u32 p, %4, 0;\n\t"
        "tcgen05.mma.cta_group::1.kind::f16 [%0], %1, %2, %3, {%5,%5,%5,%5}, p;\n\t}"
        :: "r"(d), "l"(ad), "l"(bd), "r"(idesc), "r"(en), "r"(0u) : "memory");
}
#define MBAR_INIT(a, c) \
    asm volatile("mbarrier.init.shared.b64 [%0], %1;" :: "r"(a), "r"(c) : "memory")
#define TC_COMMIT(a) \
    asm volatile("tcgen05.commit.cta_group::1.mbarrier::arrive::one.shared::cluster.b64 [%0];" :: "r"(a) : "memory")
#define TC_ALLOC(sa, n) \
    asm volatile("tcgen05.alloc.cta_group::1.sync.aligned.shared::cta.b32 [%0], %1;" :: "r"(sa), "r"(n) : "memory")
#define TC_DEALLOC(t, n) \
    asm volatile("tcgen05.dealloc.cta_group::1.sync.aligned.b32 %0, %1;" :: "r"(t), "r"(n))
#define TC_RELINQ() \
    asm volatile("tcgen05.relinquish_alloc_permit.cta_group::1.sync.aligned;")
#define TC_FENCE_AFTER()  asm volatile("tcgen05.fence::after_thread_sync;" ::: "memory")
#define TC_WAIT_LD()      asm volatile("tcgen05.wait::ld.sync.aligned;" ::: "memory")

__device__ __forceinline__ void mbar_wait(uint32_t addr, uint32_t parity) {
    asm volatile(
        "{\n\t.reg .pred P;\n\t"
        "WL_%=:\n\t"
        "mbarrier.try_wait.parity.acquire.cta.shared::cta.b64 P, [%0], %1, 0x989680;\n\t"
        "@P bra.uni WD_%=;\n\t"
        "bra.uni WL_%=;\n\t"
        "WD_%=:\n\t}"
        :: "r"(addr), "r"(parity) : "memory");
}

#define TC_LD_X32(r, a) \
    asm volatile( \
        "tcgen05.ld.sync.aligned.32x32b.x32.b32 " \
        "{%0, %1, %2, %3, %4, %5, %6, %7, %8, %9, %10, %11, %12, %13, %14, %15, " \
        " %16, %17, %18, %19, %20, %21, %22, %23, %24, %25, %26, %27, %28, %29, %30, %31}, [%32];" \
        : "=r"((r)[0]), "=r"((r)[1]), "=r"((r)[2]), "=r"((r)[3]), \
          "=r"((r)[4]), "=r"((r)[5]), "=r"((r)[6]), "=r"((r)[7]), \
          "=r"((r)[8]), "=r"((r)[9]), "=r"((r)[10]), "=r"((r)[11]), \
          "=r"((r)[12]), "=r"((r)[13]), "=r"((r)[14]), "=r"((r)[15]), \
          "=r"((r)[16]), "=r"((r)[17]), "=r"((r)[18]), "=r"((r)[19]), \
          "=r"((r)[20]), "=r"((r)[21]), "=r"((r)[22]), "=r"((r)[23]), \
          "=r"((r)[24]), "=r"((r)[25]), "=r"((r)[26]), "=r"((r)[27]), \
          "=r"((r)[28]), "=r"((r)[29]), "=r"((r)[30]), "=r"((r)[31]) \
        : "r"(a))
#endif  // HAS_TCGEN05

// ======= bf16x3 GEMM: out = (A @ B^T) variants, CTA tile 256 x NT, K-chunk 32 =======
#define SM_A 1024
#define SM_B 99328   /* 1024 + 6*16384 */
template<int NT>
__global__ __launch_bounds__(256) void mma_gemm_kernel(
    const bf16* __restrict__ Ahi, const bf16* __restrict__ Alo,
    const bf16* __restrict__ Bhi, const bf16* __restrict__ Blo,
    float* __restrict__ Cf, bf16* __restrict__ Ch, bf16* __restrict__ Cl,
    bf16* __restrict__ Dh, bf16* __restrict__ Dl,
    bf16* __restrict__ Eh, bf16* __restrict__ El,
    const float* __restrict__ Res,
    int K, int lda, int ldb, int ldc,
    int Hdim, int hshiftB,
    long long sAb, long long sAh, long long sBb, long long sBh,
    long long sCb, long long sCh, float alpha, int causal, int mode)
{
    if (causal == 1 && (int)blockIdx.y * NT > (int)blockIdx.x * 256 + 255) return;
    extern __shared__ char smem[];
    uint32_t sb = s2u(smem);
    int tid = threadIdx.x, wid = tid >> 5, lane = tid & 31;
    int z = blockIdx.z;
    int bi = z / Hdim, hi = z - bi * Hdim;

    const bf16* Ah = Ahi + bi * sAb + hi * sAh + (long long)blockIdx.x * 256 * lda;
    const bf16* Al = Alo + bi * sAb + hi * sAh + (long long)blockIdx.x * 256 * lda;
    const bf16* Bh = Bhi + bi * sBb + (long long)(hi >> hshiftB) * sBh + (long long)blockIdx.y * NT * ldb;
    const bf16* Bl = Blo + bi * sBb + (long long)(hi >> hshiftB) * sBh + (long long)blockIdx.y * NT * ldb;
    long long cbase = bi * sCb + hi * sCh + (long long)blockIdx.x * 256 * ldc
                      + (long long)blockIdx.y * NT;

    int NC = K >> 5;
    if (causal == 2) {                      // PV: keys beyond the diagonal never needed
        int lim = ((int)blockIdx.x + 1) * 8;
        if (lim < NC) NC = lim;
    }
    constexpr int NTB = NT * 64;

    auto load_stage = [&](int s, int kc) {
        long long kof = (long long)kc * 32;
        for (int i = tid; i < 2048; i += 256) {
            int p = i >> 10, rem = i & 1023, r = rem >> 2, c = rem & 3;
            const bf16* src = (p ? Al : Ah) + (long long)r * lda + kof + c * 8;
            CPA16(sb + SM_A + (s * 2 + p) * 16384 + SWZ64(r * 64 + c * 16), src);
        }
        for (int i = tid; i < 2 * NT * 4; i += 256) {
            int p = i / (NT * 4), rem = i % (NT * 4), r = rem >> 2, c = rem & 3;
            const bf16* src = (p ? Bl : Bh) + (long long)r * ldb + kof + c * 8;
            CPA16(sb + SM_B + (s * 2 + p) * NTB + SWZ64(r * 64 + c * 16), src);
        }
        CP_COMMIT();
    };

#if HAS_TCGEN05
    if (tid == 0) { MBAR_INIT(sb + 8, 1); MBAR_INIT(sb + 16, 1); MBAR_INIT(sb + 24, 1); }
    if (wid == 0) TC_ALLOC(sb, 2 * NT);
    __syncthreads();
    uint32_t tb;
    asm volatile("ld.shared.b32 %0, [%1];" : "=r"(tb) : "r"(sb));

    constexpr uint32_t IDESC =
        (1u << 4) | (1u << 7) | (1u << 10) | ((uint32_t)(NT / 8) << 17) | (8u << 24);

    load_stage(0, 0);
    load_stage(1, 1);
    int wp[3] = {0, 0, 0};
#pragma unroll 1
    for (int c = 0; c < NC; c++) {
        int s = c % 3;
        if (c + 1 < NC) CP_WAIT1(); else CP_WAIT0();
        asm volatile("fence.proxy.async.shared::cta;" ::: "memory");
        __syncthreads();
        if (wid == 0 && elect1()) {
            uint32_t AbH = sb + SM_A + (s * 2 + 0) * 16384;
            uint32_t AbL = sb + SM_A + (s * 2 + 1) * 16384;
            uint64_t dBh = mk64(sb + SM_B + (s * 2 + 0) * NTB);
            uint64_t dBl = mk64(sb + SM_B + (s * 2 + 1) * NTB);
            uint32_t en0 = (c > 0);
#pragma unroll
            for (int m = 0; m < 2; m++) {
                uint64_t dAh = mk64(AbH + m * 8192);
                uint64_t dAl = mk64(AbL + m * 8192);
                uint32_t D = tb + m * NT;
                mma_f16_ss(D, dAh + 0, dBh + 0, IDESC, en0);
                mma_f16_ss(D, dAh + 2, dBh + 2, IDESC, 1u);
                mma_f16_ss(D, dAh + 0, dBl + 0, IDESC, 1u);
                mma_f16_ss(D, dAh + 2, dBl + 2, IDESC, 1u);
                mma_f16_ss(D, dAl + 0, dBh + 0, IDESC, 1u);
                mma_f16_ss(D, dAl + 2, dBh + 2, IDESC, 1u);
            }
            TC_COMMIT(sb + 8 + s * 8);
        }
        if (c + 2 < NC) {
            int s2 = (c + 2) % 3;
            if (c >= 1) { mbar_wait(sb + 8 + s2 * 8, wp[s2] & 1); wp[s2]++; }
            load_stage(s2, c + 2);
        }
    }
    {
        int sf = (NC - 1) % 3;
        mbar_wait(sb + 8 + sf * 8, wp[sf] & 1);
    }
    TC_FENCE_AFTER();

    {
        int m = wid >> 2;
        int lrow = m * 128 + (wid & 3) * 32 + lane;
        int grow = blockIdx.x * 256 + lrow;
        if (mode == EP_F32) {
            long long rbase = cbase + (long long)lrow * ldc;
#pragma unroll 1
            for (int cb = 0; cb < NT / 32; cb++) {
                uint32_t r[32];
                TC_LD_X32(r, tb + m * NT + cb * 32);
                TC_WAIT_LD();
                long long base = rbase + cb * 32;
#pragma unroll
                for (int j = 0; j < 32; j += 4) {
                    float4 v;
                    v.x = __uint_as_float(r[j + 0]) * alpha;
                    v.y = __uint_as_float(r[j + 1]) * alpha;
                    v.z = __uint_as_float(r[j + 2]) * alpha;
                    v.w = __uint_as_float(r[j + 3]) * alpha;
                    if (Res) {
                        float4 q = *(const float4*)(Res + base + j);
                        v.x += q.x; v.y += q.y; v.z += q.z; v.w += q.w;
                    }
                    *(float4*)(Cf + base + j) = v;
                }
            }
        } else if (mode == EP_SPLIT) {
            long long rbase = cbase + (long long)lrow * ldc;
#pragma unroll 1
            for (int cb = 0; cb < NT / 32; cb++) {
                uint32_t r[32];
                TC_LD_X32(r, tb + m * NT + cb * 32);
                TC_WAIT_LD();
                float v[32];
#pragma unroll
                for (int j = 0; j < 32; j++) v[j] = __uint_as_float(r[j]);
                split_store32(Ch + rbase + cb * 32, Cl + rbase + cb * 32, v);
            }
        } else if (mode == EP_SILU) {
            long long rbase = (long long)grow * (ldc >> 1) + (long long)blockIdx.y * (NT / 2);
#pragma unroll 1
            for (int cb = 0; cb < NT / 32; cb++) {
                uint32_t r[32];
                TC_LD_X32(r, tb + m * NT + cb * 32);
                TC_WAIT_LD();
                float v[16];
#pragma unroll
                for (int q = 0; q < 16; q++) {
                    float g = __uint_as_float(r[2 * q]);
                    float u = __uint_as_float(r[2 * q + 1]);
                    v[q] = g * u / (1.0f + __expf(-g));
                }
                split_store16(Ch + rbase + cb * 16, Cl + rbase + cb * 16, v);
            }
        } else {  // EP_QKV (NT == 256)
            int y = blockIdx.y;
            if (y >= 12) {
                // V tile: transposed split store directly into VT[(b*1024+ch)*1024 + s]
                int b = grow >> 10, scol = grow & 1023;
                long long vb = (long long)b * 1024 * 1024 + scol;
#pragma unroll 1
                for (int cb = 0; cb < 8; cb++) {
                    uint32_t r[32];
                    TC_LD_X32(r, tb + m * NT + cb * 32);
                    TC_WAIT_LD();
                    int ch0 = (y - 12) * 256 + cb * 32;
#pragma unroll
                    for (int j = 0; j < 32; j++) {
                        bf16 h, l;
                        split1(__uint_as_float(r[j]), h, l);
                        long long o = vb + (long long)(ch0 + j) * 1024;
                        Eh[o] = h; El[o] = l;
                    }
                }
            } else {
                int pos = grow & (SS - 1);
                const int pps[4] = {0, 1, 4, 5};
#pragma unroll 1
                for (int t = 0; t < 4; t++) {
                    int pp = pps[t];
                    uint32_t r1[32], r2[32];
                    TC_LD_X32(r1, tb + m * NT + pp * 32);
                    TC_LD_X32(r2, tb + m * NT + (pp + 2) * 32);
                    TC_WAIT_LD();
                    int ibase = (pp & 1) * 32;
                    int col0 = y * 256 + ((pp >> 2) << 7);
                    float v1[32], v2[32];
#pragma unroll
                    for (int j = 0; j < 32; j++) {
                        rope1(pos, ibase + j,
                              __uint_as_float(r1[j]), __uint_as_float(r2[j]),
                              v1[j], v2[j]);
                    }
                    if (y < 8) {
                        long long ob = (long long)grow * 2048 + col0 + ibase;
                        split_store32(Ch + ob, Cl + ob, v1);
                        split_store32(Ch + ob + 64, Cl + ob + 64, v2);
                    } else {
                        long long ob = (long long)grow * 1024 + (col0 - 2048) + ibase;
                        split_store32(Dh + ob, Dl + ob, v1);
                        split_store32(Dh + ob + 64, Dl + ob + 64, v2);
                    }
                }
            }
        }
    }
    __syncthreads();
    if (wid == 0) { TC_RELINQ(); TC_DEALLOC(tb, 2 * NT); }

#else
    // ------- mma.sync fallback (compute_103-legal; not selected on sm_103a) -------
    int g = lane >> 2, tg = lane & 3;
#pragma unroll 1
    for (int nh = 0; nh < NT / 128; nh++) {
        float acc[2][16][4];
#pragma unroll
        for (int g2 = 0; g2 < 2; g2++)
#pragma unroll
            for (int i = 0; i < 16; i++)
#pragma unroll
                for (int j = 0; j < 4; j++) acc[g2][i][j] = 0.f;
#pragma unroll 1
        for (int c = 0; c < NC; c++) {
            __syncthreads();
            load_stage(0, c);
            CP_WAIT0();
            __syncthreads();
#pragma unroll 1
            for (int pass = 0; pass < 3; pass++) {
                int pa = (pass == 2) ? 1 : 0;
                int pb = (pass == 1) ? 1 : 0;
                uint32_t At = sb + SM_A + pa * 16384;
                uint32_t Bt = sb + SM_B + pb * NTB;
#pragma unroll 1
                for (int g2 = 0; g2 < 2; g2++) {
                    int R = (wid * 2 + g2) * 16;
#pragma unroll
                    for (int ks = 0; ks < 2; ks++) {
                        int k0 = ks * 16;
                        uint32_t a0 = lds32(At + SWZ64((R + g) * 64 + (k0 + tg * 2) * 2));
                        uint32_t a1 = lds32(At + SWZ64((R + g + 8) * 64 + (k0 + tg * 2) * 2));
                        uint32_t a2 = lds32(At + SWZ64((R + g) * 64 + (k0 + 8 + tg * 2) * 2));
                        uint32_t a3 = lds32(At + SWZ64((R + g + 8) * 64 + (k0 + 8 + tg * 2) * 2));
#pragma unroll
                        for (int nt = 0; nt < 16; nt++) {
                            int br = nh * 128 + nt * 8 + g;
                            uint32_t b0 = lds32(Bt + SWZ64(br * 64 + (k0 + tg * 2) * 2));
                            uint32_t b1 = lds32(Bt + SWZ64(br * 64 + (k0 + 8 + tg * 2) * 2));
                            asm volatile(
                                "mma.sync.aligned.m16n8k16.row.col.f32.bf16.bf16.f32 "
                                "{%0,%1,%2,%3}, {%4,%5,%6,%7}, {%8,%9}, {%0,%1,%2,%3};"
                                : "+f"(acc[g2][nt][0]), "+f"(acc[g2][nt][1]),
                                  "+f"(acc[g2][nt][2]), "+f"(acc[g2][nt][3])
                                : "r"(a0), "r"(a1), "r"(a2), "r"(a3), "r"(b0), "r"(b1));
                        }
                    }
                }
            }
        }
#pragma unroll 1
        for (int g2 = 0; g2 < 2; g2++) {
            int R = (wid * 2 + g2) * 16;
#pragma unroll 1
            for (int rh = 0; rh < 2; rh++) {
                int lrow = R + g + rh * 8;
                int grow = blockIdx.x * 256 + lrow;
                if (mode == EP_F32) {
#pragma unroll
                    for (int nt = 0; nt < 16; nt++) {
                        int col = nh * 128 + nt * 8 + tg * 2;
                        long long o = cbase + (long long)lrow * ldc + col;
                        float a0 = acc[g2][nt][rh * 2] * alpha;
                        float a1 = acc[g2][nt][rh * 2 + 1] * alpha;
                        if (Res) { a0 += Res[o]; a1 += Res[o + 1]; }
                        Cf[o] = a0; Cf[o + 1] = a1;
                    }
                } else if (mode == EP_QKV && blockIdx.y >= 12) {
                    int b = grow >> 10, scol = grow & 1023;
                    long long vb = (long long)b * 1024 * 1024 + scol;
#pragma unroll
                    for (int nt = 0; nt < 16; nt++) {
#pragma unroll
                        for (int k = 0; k < 2; k++) {
                            int ch = (blockIdx.y - 12) * 256 + nh * 128 + nt * 8 + tg * 2 + k;
                            bf16 h, l;
                            split1(acc[g2][nt][rh * 2 + k], h, l);
                            long long o = vb + (long long)ch * 1024;
                            Eh[o] = h; El[o] = l;
                        }
                    }
                } else if (mode == EP_SPLIT) {
#pragma unroll
                    for (int nt = 0; nt < 16; nt++) {
                        int col = nh * 128 + nt * 8 + tg * 2;
                        long long o = cbase + (long long)lrow * ldc + col;
                        bf16 h, l;
                        split1(acc[g2][nt][rh * 2], h, l);     Ch[o] = h;     Cl[o] = l;
                        split1(acc[g2][nt][rh * 2 + 1], h, l); Ch[o + 1] = h; Cl[o + 1] = l;
                    }
                } else if (mode == EP_SILU) {
#pragma unroll
                    for (int nt = 0; nt < 16; nt++) {
                        int col = blockIdx.y * NT + nh * 128 + nt * 8 + tg * 2;
                        float gg = acc[g2][nt][rh * 2], uu = acc[g2][nt][rh * 2 + 1];
                        float s = gg * uu / (1.0f + __expf(-gg));
                        long long o = (long long)grow * (ldc >> 1) + col / 2;
                        bf16 h, l; split1(s, h, l);
                        Ch[o] = h; Cl[o] = l;
                    }
                } else {
                    int pos = grow & (SS - 1);
#pragma unroll
                    for (int nt = 0; nt < 8; nt++) {
#pragma unroll
                        for (int k = 0; k < 2; k++) {
                            int i = nt * 8 + tg * 2 + k;
                            float x1 = acc[g2][nt][rh * 2 + k];
                            float x2 = acc[g2][nt + 8][rh * 2 + k];
                            float o1, o2;
                            rope1(pos, i, x1, x2, o1, o2);
                            int col0 = blockIdx.y * 256 + nh * 128;
                            bf16 h, l;
                            if (blockIdx.y < 8) {
                                long long ob = (long long)grow * 2048 + col0 + i;
                                split1(o1, h, l); Ch[ob] = h;      Cl[ob] = l;
                                split1(o2, h, l); Ch[ob + 64] = h; Cl[ob + 64] = l;
                            } else {
                                long long ob = (long long)grow * 1024 + (col0 - 2048) + i;
                                split1(o1, h, l); Dh[ob] = h;      Dl[ob] = l;
                                split1(o2, h, l); Dh[ob + 64] = h; Dl[ob + 64] = l;
                            }
                        }
                    }
                }
            }
        }
    }
#endif
}

// ================= elementwise kernels =================
__global__ void embed_kernel(const int* __restrict__ ids, const float* __restrict__ embed,
                             float* __restrict__ X) {
    int t = blockIdx.x;
    int id = ids[t];
    const float4* src = (const float4*)(embed + (long long)id * DD);
    float4* dst = (float4*)(X + (long long)t * DD);
    for (int i = threadIdx.x; i < DD / 4; i += blockDim.x) dst[i] = src[i];
}

__global__ void rmsnorm_split_kernel(const float* __restrict__ X, const float* __restrict__ w,
                                     bf16* __restrict__ oh, bf16* __restrict__ ol) {
    int t = blockIdx.x;
    const float* x = X + (long long)t * DD;
    float ss = 0.f;
    for (int i = threadIdx.x; i < DD; i += 256) { float v = x[i]; ss += v * v; }
    __shared__ float red[256];
    red[threadIdx.x] = ss;
    __syncthreads();
    for (int s = 128; s > 0; s >>= 1) {
        if (threadIdx.x < s) red[threadIdx.x] += red[threadIdx.x + s];
        __syncthreads();
    }
    float scale = rsqrtf(red[0] * (1.0f / DD) + 1e-6f);
    for (int i = threadIdx.x; i < DD; i += 256) {
        float v = x[i] * scale * w[i];
        bf16 h, l; split1(v, h, l);
        oh[(long long)t * DD + i] = h;
        ol[(long long)t * DD + i] = l;
    }
}

__global__ void qkvsplit_kernel(const float* __restrict__ wq, const float* __restrict__ wk,
                                const float* __restrict__ wv,
                                bf16* __restrict__ oh, bf16* __restrict__ ol) {
    long long off = ((long long)blockIdx.x * blockDim.x + threadIdx.x) * 8;
    if (off >= (long long)4096 * DD) return;
    const float* src;
    long long so;
    if (off < (long long)2048 * DD)      { src = wq; so = off; }
    else if (off < (long long)3072 * DD) { src = wk; so = off - (long long)2048 * DD; }
    else                                 { src = wv; so = off - (long long)3072 * DD; }
    float4 a = *(const float4*)(src + so);
    float4 b = *(const float4*)(src + so + 4);
    split_store8(oh + off, ol + off, a, b);
}

__global__ void gusplit_kernel(const float* __restrict__ wg, const float* __restrict__ wu,
                               bf16* __restrict__ oh, bf16* __restrict__ ol) {
    long long off = ((long long)blockIdx.x * blockDim.x + threadIdx.x) * 8;
    if (off >= (long long)16384 * DD) return;
    int orow = (int)(off >> 11);
    int col = (int)(off & 2047);
    int j = orow >> 1;
    const float* src = (orow & 1) ? wu : wg;
    long long so = (long long)j * DD + col;
    float4 a = *(const float4*)(src + so);
    float4 b = *(const float4*)(src + so + 4);
    split_store8(oh + off, ol + off, a, b);
}

__global__ void flat8split_kernel(const float* __restrict__ in,
                                  bf16* __restrict__ oh, bf16* __restrict__ ol, long long n) {
    long long off = ((long long)blockIdx.x * blockDim.x + threadIdx.x) * 8;
    if (off >= n) return;
    float4 a = *(const float4*)(in + off);
    float4 b = *(const float4*)(in + off + 4);
    split_store8(oh + off, ol + off, a, b);
}

__global__ void softmax_kernel(const float* __restrict__ SC,
                               bf16* __restrict__ Ph, bf16* __restrict__ Pl) {
    __shared__ float red[256];
    __shared__ float ex[SS];
    long long r = blockIdx.x;
    int q = (int)(r & (SS - 1));
    int kend = ((q >> 8) + 1) << 8;
    const float* row = SC + r * SS;
    int tid = threadIdx.x;
    float sum = 0.f;
    for (int k = tid; k < kend; k += 256) {
        float e = (k <= q) ? __expf(row[k]) : 0.f;
        ex[k] = e;
        sum += e;
    }
    red[tid] = sum; __syncthreads();
    for (int s = 128; s > 0; s >>= 1) {
        if (tid < s) red[tid] += red[tid + s];
        __syncthreads();
    }
    float inv = 1.0f / red[0];
    bf16* ph = Ph + r * SS;
    bf16* pl = Pl + r * SS;
    for (int k = tid * 2; k < kend; k += 512) {
        uint32_t lo;
        uint32_t hi = packsplit(ex[k] * inv, ex[k + 1] * inv, lo);
        *(uint32_t*)(ph + k) = hi;
        *(uint32_t*)(pl + k) = lo;
    }
}

// ================= host =================
template<int NT>
static void launch_gemm(dim3 grid,
                        const bf16* Ah, const bf16* Al, const bf16* Bh, const bf16* Bl,
                        float* Cf, bf16* Ch, bf16* Cl, bf16* Dh, bf16* Dl,
                        bf16* Eh, bf16* El,
                        const float* Res,
                        int K, int lda, int ldb, int ldc,
                        int Hdim, int hshift,
                        long long sAb, long long sAh, long long sBb, long long sBh,
                        long long sCb, long long sCh, float alpha, int causal, int mode) {
    constexpr int SMEM = 99328 + 6 * NT * 64;
    cudaFuncSetAttribute(mma_gemm_kernel<NT>, cudaFuncAttributeMaxDynamicSharedMemorySize, SMEM);
    mma_gemm_kernel<NT><<<grid, 256, SMEM>>>(Ah, Al, Bh, Bl, Cf, Ch, Cl, Dh, Dl, Eh, El, Res,
                                             K, lda, ldb, ldc, Hdim, hshift,
                                             sAb, sAh, sBb, sBh, sCb, sCh,
                                             alpha, causal, mode);
}

extern "C" void kernel_launch(void* const* d_in, const int* in_sizes, int n_in,
                              void* d_out, int out_size) {
    const int*   ids   = (const int*)d_in[0];
    const float* embed = (const float*)d_in[3];
    const float* ln1   = (const float*)d_in[4];
    const float* wq    = (const float*)d_in[5];
    const float* wk    = (const float*)d_in[6];
    const float* wv    = (const float*)d_in[7];
    const float* wo    = (const float*)d_in[8];
    const float* ln2   = (const float*)d_in[9];
    const float* wg    = (const float*)d_in[10];
    const float* wu    = (const float*)d_in[11];
    const float* wd    = (const float*)d_in[12];
    const float* nrm   = (const float*)d_in[13];
    const float* lmh   = (const float*)d_in[14];
    float* out = (float*)d_out;

    float *X, *SC;
    bf16 *XNh, *XNl, *Qh, *Ql, *Kh, *Kl, *VTh, *VTl, *Ph, *Pl, *AOh, *AOl, *Gh, *Gl;
    bf16 *Lmhh, *Lmhl;
    bf16 *Wqkvh[LL], *Wqkvl[LL], *Woh[LL], *Wol[LL], *Wguh[LL], *Wgul[LL], *Wdh[LL], *Wdl[LL];
    cudaGetSymbolAddress((void**)&X, g_X);
    cudaGetSymbolAddress((void**)&SC, g_SC);
    cudaGetSymbolAddress((void**)&XNh, g_XNh);   cudaGetSymbolAddress((void**)&XNl, g_XNl);
    cudaGetSymbolAddress((void**)&Qh, g_Qh);     cudaGetSymbolAddress((void**)&Ql, g_Ql);
    cudaGetSymbolAddress((void**)&Kh, g_Kh);     cudaGetSymbolAddress((void**)&Kl, g_Kl);
    cudaGetSymbolAddress((void**)&VTh, g_VTh);   cudaGetSymbolAddress((void**)&VTl, g_VTl);
    cudaGetSymbolAddress((void**)&Ph, g_Ph);     cudaGetSymbolAddress((void**)&Pl, g_Pl);
    cudaGetSymbolAddress((void**)&AOh, g_AOh);   cudaGetSymbolAddress((void**)&AOl, g_AOl);
    cudaGetSymbolAddress((void**)&Gh, g_Gh);     cudaGetSymbolAddress((void**)&Gl, g_Gl);
    cudaGetSymbolAddress((void**)&Lmhh, g_Lmhh); cudaGetSymbolAddress((void**)&Lmhl, g_Lmhl);
    {
        bf16 *p;
        cudaGetSymbolAddress((void**)&p, g_Wqkvh);
        for (int l = 0; l < LL; l++) Wqkvh[l] = p + (size_t)l * 4096 * DD;
        cudaGetSymbolAddress((void**)&p, g_Wqkvl);
        for (int l = 0; l < LL; l++) Wqkvl[l] = p + (size_t)l * 4096 * DD;
        cudaGetSymbolAddress((void**)&p, g_Woh);
        for (int l = 0; l < LL; l++) Woh[l] = p + (size_t)l * DD * DD;
        cudaGetSymbolAddress((void**)&p, g_Wol);
        for (int l = 0; l < LL; l++) Wol[l] = p + (size_t)l * DD * DD;
        cudaGetSymbolAddress((void**)&p, g_Wguh);
        for (int l = 0; l < LL; l++) Wguh[l] = p + (size_t)l * 16384 * DD;
        cudaGetSymbolAddress((void**)&p, g_Wgul);
        for (int l = 0; l < LL; l++) Wgul[l] = p + (size_t)l * 16384 * DD;
        cudaGetSymbolAddress((void**)&p, g_Wdh);
        for (int l = 0; l < LL; l++) Wdh[l] = p + (size_t)l * DD * FF_;
        cudaGetSymbolAddress((void**)&p, g_Wdl);
        for (int l = 0; l < LL; l++) Wdl[l] = p + (size_t)l * DD * FF_;
    }

    const float scale = 0.08838834764831845f;  // 1/sqrt(128)

    static cudaStream_t sSide = nullptr;
    static cudaEvent_t evRoot = nullptr;
    static cudaEvent_t evSplit[LL * 4 + 1];
    if (sSide == nullptr) {
        cudaStreamCreateWithFlags(&sSide, cudaStreamNonBlocking);
        cudaEventCreateWithFlags(&evRoot, cudaEventDisableTiming);
        for (int i = 0; i < LL * 4 + 1; i++)
            cudaEventCreateWithFlags(&evSplit[i], cudaEventDisableTiming);
    }

    // fork: all weight splits run on the side stream (depend only on inputs)
    cudaEventRecord(evRoot, 0);
    cudaStreamWaitEvent(sSide, evRoot, 0);
    for (int l = 0; l < LL; l++) {
        qkvsplit_kernel<<<4096, 256, 0, sSide>>>(
            wq + (long long)l * DD * DD, wk + (long long)l * KVD * DD,
            wv + (long long)l * KVD * DD, Wqkvh[l], Wqkvl[l]);
        cudaEventRecord(evSplit[l * 4 + 0], sSide);
        flat8split_kernel<<<2048, 256, 0, sSide>>>(
            wo + (long long)l * DD * DD, Woh[l], Wol[l], (long long)DD * DD);
        cudaEventRecord(evSplit[l * 4 + 1], sSide);
        gusplit_kernel<<<16384, 256, 0, sSide>>>(
            wg + (long long)l * FF_ * DD, wu + (long long)l * FF_ * DD, Wguh[l], Wgul[l]);
        cudaEventRecord(evSplit[l * 4 + 2], sSide);
        flat8split_kernel<<<8192, 256, 0, sSide>>>(
            wd + (long long)l * DD * FF_, Wdh[l], Wdl[l], (long long)DD * FF_);
        cudaEventRecord(evSplit[l * 4 + 3], sSide);
    }
    flat8split_kernel<<<32000, 256, 0, sSide>>>(lmh, Lmhh, Lmhl, (long long)VV * DD);
    cudaEventRecord(evSplit[LL * 4], sSide);

    // ---- main stream ----
    embed_kernel<<<TT, 256>>>(ids, embed, X);

    for (int l = 0; l < LL; l++) {
        rmsnorm_split_kernel<<<TT, 256>>>(X, ln1 + l * DD, XNh, XNl);

        cudaStreamWaitEvent(0, evSplit[l * 4 + 0], 0);
        // QKV GEMM: fused rope/split (Q,K) + transposed V split (VT) epilogue
        launch_gemm<256>(dim3(8, 16, 1), XNh, XNl, Wqkvh[l], Wqkvl[l],
                         nullptr, Qh, Ql, Kh, Kl, VTh, VTl, nullptr,
                         DD, DD, DD, 4096, 1, 0, 0, 0, 0, 0, 0, 0, 1.0f, 0, EP_QKV);

        // scores = scale * Q @ K^T (causal tile skip)
        launch_gemm<256>(dim3(4, 4, 32), Qh, Ql, Kh, Kl,
                         SC, nullptr, nullptr, nullptr, nullptr, nullptr, nullptr, nullptr,
                         HD, DD, KVD, SS, HH, 1,
                         (long long)SS * DD, (long long)HD,
                         (long long)SS * KVD, (long long)HD,
                         (long long)HH * SS * SS, (long long)SS * SS, scale, 1, EP_F32);

        softmax_kernel<<<BBX * HH * SS, 256>>>(SC, Ph, Pl);

        // AO = P @ VT^T -> bf16 hi/lo directly (causal K-chunk limit)
        launch_gemm<128>(dim3(4, 1, 32), Ph, Pl, VTh, VTl,
                         nullptr, AOh, AOl, nullptr, nullptr, nullptr, nullptr, nullptr,
                         SS, SS, SS, DD, HH, 1,
                         (long long)HH * SS * SS, (long long)SS * SS,
                         (long long)KVH * HD * SS, (long long)HD * SS,
                         (long long)SS * DD, (long long)HD, 1.0f, 2, EP_SPLIT);

        cudaStreamWaitEvent(0, evSplit[l * 4 + 1], 0);
        // X = X + AO @ Wo^T
        launch_gemm<128>(dim3(8, 16, 1), AOh, AOl, Woh[l], Wol[l],
                         X, nullptr, nullptr, nullptr, nullptr, nullptr, nullptr, X,
                         DD, DD, DD, DD, 1, 0, 0, 0, 0, 0, 0, 0, 1.0f, 0, EP_F32);

        rmsnorm_split_kernel<<<TT, 256>>>(X, ln2 + l * DD, XNh, XNl);

        cudaStreamWaitEvent(0, evSplit[l * 4 + 2], 0);
        // G = silu(XN@Wg^T) * (XN@Wu^T) fused in epilogue
        launch_gemm<256>(dim3(8, 64, 1), XNh, XNl, Wguh[l], Wgul[l],
                         nullptr, Gh, Gl, nullptr, nullptr, nullptr, nullptr, nullptr,
                         DD, DD, DD, 16384, 1, 0, 0, 0, 0, 0, 0, 0, 1.0f, 0, EP_SILU);

        cudaStreamWaitEvent(0, evSplit[l * 4 + 3], 0);
        // X = X + G @ Wd^T
        launch_gemm<128>(dim3(8, 16, 1), Gh, Gl, Wdh[l], Wdl[l],
                         X, nullptr, nullptr, nullptr, nullptr, nullptr, nullptr, X,
                         FF_, FF_, FF_, DD, 1, 0, 0, 0, 0, 0, 0, 0, 1.0f, 0, EP_F32);
    }

    rmsnorm_split_kernel<<<TT, 256>>>(X, nrm, XNh, XNl);
    cudaStreamWaitEvent(0, evSplit[LL * 4], 0);
    // logits = XN @ lm_head^T
    launch_gemm<256>(dim3(8, 125, 1), XNh, XNl, Lmhh, Lmhl,
                     out, nullptr, nullptr, nullptr, nullptr, nullptr, nullptr, nullptr,
                     DD, DD, DD, VV, 1, 0, 0, 0, 0, 0, 0, 0, 1.0f, 0, EP_F32);
}

// round 16
// speedup vs baseline: 1.5642x; 1.0447x over previous
#include <cuda_runtime.h>
#include <cuda_bf16.h>
#include <math.h>
#include <stdint.h>

// ---------------- problem constants ----------------
#define TT   2048
#define BBX  2
#define SS   1024
#define DD   2048
#define HH   16
#define KVH  8
#define HD   128
#define KVD  1024
#define FF_  8192
#define LL   4
#define VV   32000

typedef __nv_bfloat16 bf16;

#if defined(__CUDA_ARCH_FEAT_SM103_ALL) || defined(__CUDA_ARCH_FEAT_SM100_ALL) || defined(__CUDA_ARCH_FEAT_SM101_ALL)
#define HAS_TCGEN05 1
#else
#define HAS_TCGEN05 0
#endif

// epilogue modes
#define EP_F32    0
#define EP_SILU   1
#define EP_SPLIT  2
#define EP_QKV    3
#define EP_EXP    4   // scores: e=exp(acc*alpha) masked causal; split->Ch/Cl; rowsum atomics->Cf
#define EP_PVNORM 5   // PV: acc * 1/rowsum[row] -> split Ch/Cl
// causal modes: 0 none; 1 = N-tile skip (scores); 2 = K-chunk limit per M-tile (PV)

// ---------------- scratch ----------------
__device__ __align__(256) float g_X  [TT * DD];
__device__ __align__(256) float g_RS [BBX * HH * SS];

__device__ __align__(256) bf16 g_XNh[TT * DD],  g_XNl[TT * DD];
__device__ __align__(256) bf16 g_Qh [TT * DD],  g_Ql [TT * DD];
__device__ __align__(256) bf16 g_Kh [TT * KVD], g_Kl [TT * KVD];
__device__ __align__(256) bf16 g_VTh[TT * KVD], g_VTl[TT * KVD];
__device__ __align__(256) bf16 g_Ph [(size_t)BBX * HH * SS * SS];
__device__ __align__(256) bf16 g_Pl [(size_t)BBX * HH * SS * SS];
__device__ __align__(256) bf16 g_AOh[TT * DD],  g_AOl[TT * DD];
__device__ __align__(256) bf16 g_Gh [(size_t)TT * FF_], g_Gl[(size_t)TT * FF_];

// per-layer weight buffers (no reuse across layers -> no WAR hazard vs side stream)
__device__ __align__(256) bf16 g_Wqkvh[LL][(size_t)4096 * DD],  g_Wqkvl[LL][(size_t)4096 * DD];
__device__ __align__(256) bf16 g_Woh  [LL][(size_t)DD * DD],    g_Wol  [LL][(size_t)DD * DD];
__device__ __align__(256) bf16 g_Wguh [LL][(size_t)16384 * DD], g_Wgul [LL][(size_t)16384 * DD];
__device__ __align__(256) bf16 g_Wdh  [LL][(size_t)DD * FF_],   g_Wdl  [LL][(size_t)DD * FF_];
__device__ __align__(256) bf16 g_Lmhh [(size_t)VV * DD],        g_Lmhl [(size_t)VV * DD];

// ---------------- helpers ----------------
__device__ __forceinline__ uint32_t s2u(const void* p) {
    uint32_t a;
    asm("{ .reg .u64 t; cvta.to.shared.u64 t, %1; cvt.u32.u64 %0, t; }" : "=r"(a) : "l"(p));
    return a;
}
__device__ __forceinline__ uint32_t elect1() {
    uint32_t r;
    asm volatile("{\n\t.reg .pred p;\n\telect.sync _|p, 0xFFFFFFFF;\n\tselp.b32 %0, 1, 0, p;\n\t}" : "=r"(r));
    return r;
}
__device__ __forceinline__ uint32_t lds32(uint32_t a) {
    uint32_t v;
    asm volatile("ld.shared.b32 %0, [%1];" : "=r"(v) : "r"(a));
    return v;
}
#define SWZ64(x) ((x) ^ (((x) >> 3) & 0x30))

#define CPA16(d, s) \
    asm volatile("cp.async.cg.shared.global [%0], [%1], 16;" :: "r"(d), "l"(__cvta_generic_to_global(s)))
#define CP_COMMIT()  asm volatile("cp.async.commit_group;" ::: "memory")
#define CP_WAIT1()   asm volatile("cp.async.wait_group 1;" ::: "memory")
#define CP_WAIT0()   asm volatile("cp.async.wait_group 0;" ::: "memory")

__device__ __forceinline__ void split1(float v, bf16& h, bf16& l) {
    h = __float2bfloat16(v);
    l = __float2bfloat16(v - __bfloat162float(h));
}
__device__ __forceinline__ uint32_t packsplit(float a, float b, uint32_t& lo) {
    bf16 ha = __float2bfloat16(a), hb = __float2bfloat16(b);
    bf16 la = __float2bfloat16(a - __bfloat162float(ha));
    bf16 lb = __float2bfloat16(b - __bfloat162float(hb));
    lo = (uint32_t)*(uint16_t*)&la | ((uint32_t)*(uint16_t*)&lb << 16);
    return (uint32_t)*(uint16_t*)&ha | ((uint32_t)*(uint16_t*)&hb << 16);
}
__device__ __forceinline__ void split_store8(bf16* dh, bf16* dl, float4 a, float4 b) {
    uint32_t l0, l1, l2, l3;
    uint32_t h0 = packsplit(a.x, a.y, l0);
    uint32_t h1 = packsplit(a.z, a.w, l1);
    uint32_t h2 = packsplit(b.x, b.y, l2);
    uint32_t h3 = packsplit(b.z, b.w, l3);
    *(uint4*)dh = make_uint4(h0, h1, h2, h3);
    *(uint4*)dl = make_uint4(l0, l1, l2, l3);
}
__device__ __forceinline__ void split_store32(bf16* dh, bf16* dl, const float* v) {
    uint32_t wh[16], wl[16];
#pragma unroll
    for (int q = 0; q < 16; q++) wh[q] = packsplit(v[2*q], v[2*q+1], wl[q]);
    uint4* H = (uint4*)dh; uint4* L = (uint4*)dl;
#pragma unroll
    for (int q = 0; q < 4; q++) {
        H[q] = make_uint4(wh[4*q], wh[4*q+1], wh[4*q+2], wh[4*q+3]);
        L[q] = make_uint4(wl[4*q], wl[4*q+1], wl[4*q+2], wl[4*q+3]);
    }
}
__device__ __forceinline__ void split_store16(bf16* dh, bf16* dl, const float* v) {
    uint32_t wh[8], wl[8];
#pragma unroll
    for (int q = 0; q < 8; q++) wh[q] = packsplit(v[2*q], v[2*q+1], wl[q]);
    uint4* H = (uint4*)dh; uint4* L = (uint4*)dl;
#pragma unroll
    for (int q = 0; q < 2; q++) {
        H[q] = make_uint4(wh[4*q], wh[4*q+1], wh[4*q+2], wh[4*q+3]);
        L[q] = make_uint4(wl[4*q], wl[4*q+1], wl[4*q+2], wl[4*q+3]);
    }
}
__device__ __forceinline__ void rope1(int pos, int i, float x1, float x2, float& o1, float& o2) {
    float freq = __expf(-(float)(2 * i) * (1.0f / 128.0f) * 9.210340371976184f);
    float sn, cs;
    sincosf((float)pos * freq, &sn, &cs);
    o1 = x1 * cs - x2 * sn;
    o2 = x1 * sn + x2 * cs;
}

#if HAS_TCGEN05
constexpr uint64_t DESCBASE64 =
    (uint64_t(4) << 61) | (uint64_t(1) << 46) | (uint64_t(32) << 32) | (uint64_t(1) << 16);
__device__ __forceinline__ uint64_t mk64(uint32_t a) {
    return DESCBASE64 | ((uint64_t)(a >> 4) & 0x3FFF);
}
__device__ __forceinline__ void mma_f16_ss(uint32_t d, uint64_t ad, uint64_t bd,
                                           uint32_t idesc, uint32_t en) {
    asm volatile(
        "{\n\t.reg .pred p;\n\tsetp.ne.u32 p, %4, 0;\n\t"
        "tcgen05.mma.cta_group::1.kind::f16 [%0], %1, %2, %3, {%5,%5,%5,%5}, p;\n\t}"
        :: "r"(d), "l"(ad), "l"(bd), "r"(idesc), "r"(en), "r"(0u) : "memory");
}
#define MBAR_INIT(a, c) \
    asm volatile("mbarrier.init.shared.b64 [%0], %1;" :: "r"(a), "r"(c) : "memory")
#define TC_COMMIT(a) \
    asm volatile("tcgen05.commit.cta_group::1.mbarrier::arrive::one.shared::cluster.b64 [%0];" :: "r"(a) : "memory")
#define TC_ALLOC(sa, n) \
    asm volatile("tcgen05.alloc.cta_group::1.sync.aligned.shared::cta.b32 [%0], %1;" :: "r"(sa), "r"(n) : "memory")
#define TC_DEALLOC(t, n) \
    asm volatile("tcgen05.dealloc.cta_group::1.sync.aligned.b32 %0, %1;" :: "r"(t), "r"(n))
#define TC_RELINQ() \
    asm volatile("tcgen05.relinquish_alloc_permit.cta_group::1.sync.aligned;")
#define TC_FENCE_AFTER()  asm volatile("tcgen05.fence::after_thread_sync;" ::: "memory")
#define TC_WAIT_LD()      asm volatile("tcgen05.wait::ld.sync.aligned;" ::: "memory")

__device__ __forceinline__ void mbar_wait(uint32_t addr, uint32_t parity) {
    asm volatile(
        "{\n\t.reg .pred P;\n\t"
        "WL_%=:\n\t"
        "mbarrier.try_wait.parity.acquire.cta.shared::cta.b64 P, [%0], %1, 0x989680;\n\t"
        "@P bra.uni WD_%=;\n\t"
        "bra.uni WL_%=;\n\t"
        "WD_%=:\n\t}"
        :: "r"(addr), "r"(parity) : "memory");
}

#define TC_LD_X32(r, a) \
    asm volatile( \
        "tcgen05.ld.sync.aligned.32x32b.x32.b32 " \
        "{%0, %1, %2, %3, %4, %5, %6, %7, %8, %9, %10, %11, %12, %13, %14, %15, " \
        " %16, %17, %18, %19, %20, %21, %22, %23, %24, %25, %26, %27, %28, %29, %30, %31}, [%32];" \
        : "=r"((r)[0]), "=r"((r)[1]), "=r"((r)[2]), "=r"((r)[3]), \
          "=r"((r)[4]), "=r"((r)[5]), "=r"((r)[6]), "=r"((r)[7]), \
          "=r"((r)[8]), "=r"((r)[9]), "=r"((r)[10]), "=r"((r)[11]), \
          "=r"((r)[12]), "=r"((r)[13]), "=r"((r)[14]), "=r"((r)[15]), \
          "=r"((r)[16]), "=r"((r)[17]), "=r"((r)[18]), "=r"((r)[19]), \
          "=r"((r)[20]), "=r"((r)[21]), "=r"((r)[22]), "=r"((r)[23]), \
          "=r"((r)[24]), "=r"((r)[25]), "=r"((r)[26]), "=r"((r)[27]), \
          "=r"((r)[28]), "=r"((r)[29]), "=r"((r)[30]), "=r"((r)[31]) \
        : "r"(a))
#endif  // HAS_TCGEN05

// ======= bf16x3 GEMM: out = (A @ B^T) variants, CTA tile 256 x NT, K-chunk 32 =======
#define SM_A 1024
#define SM_B 99328   /* 1024 + 6*16384 */
template<int NT>
__global__ __launch_bounds__(256) void mma_gemm_kernel(
    const bf16* __restrict__ Ahi, const bf16* __restrict__ Alo,
    const bf16* __restrict__ Bhi, const bf16* __restrict__ Blo,
    float* __restrict__ Cf, bf16* __restrict__ Ch, bf16* __restrict__ Cl,
    bf16* __restrict__ Dh, bf16* __restrict__ Dl,
    bf16* __restrict__ Eh, bf16* __restrict__ El,
    const float* __restrict__ Res,
    int K, int lda, int ldb, int ldc,
    int Hdim, int hshiftB,
    long long sAb, long long sAh, long long sBb, long long sBh,
    long long sCb, long long sCh, float alpha, int causal, int mode)
{
    if (causal == 1 && (int)blockIdx.y * NT > (int)blockIdx.x * 256 + 255) return;
    extern __shared__ char smem[];
    uint32_t sb = s2u(smem);
    int tid = threadIdx.x, wid = tid >> 5, lane = tid & 31;
    int z = blockIdx.z;
    int bi = z / Hdim, hi = z - bi * Hdim;

    const bf16* Ah = Ahi + bi * sAb + hi * sAh + (long long)blockIdx.x * 256 * lda;
    const bf16* Al = Alo + bi * sAb + hi * sAh + (long long)blockIdx.x * 256 * lda;
    const bf16* Bh = Bhi + bi * sBb + (long long)(hi >> hshiftB) * sBh + (long long)blockIdx.y * NT * ldb;
    const bf16* Bl = Blo + bi * sBb + (long long)(hi >> hshiftB) * sBh + (long long)blockIdx.y * NT * ldb;
    long long cbase = bi * sCb + hi * sCh + (long long)blockIdx.x * 256 * ldc
                      + (long long)blockIdx.y * NT;

    int NC = K >> 5;
    if (causal == 2) {                      // PV: keys beyond the diagonal never needed
        int lim = ((int)blockIdx.x + 1) * 8;
        if (lim < NC) NC = lim;
    }
    constexpr int NTB = NT * 64;

    auto load_stage = [&](int s, int kc) {
        long long kof = (long long)kc * 32;
        for (int i = tid; i < 2048; i += 256) {
            int p = i >> 10, rem = i & 1023, r = rem >> 2, c = rem & 3;
            const bf16* src = (p ? Al : Ah) + (long long)r * lda + kof + c * 8;
            CPA16(sb + SM_A + (s * 2 + p) * 16384 + SWZ64(r * 64 + c * 16), src);
        }
        for (int i = tid; i < 2 * NT * 4; i += 256) {
            int p = i / (NT * 4), rem = i % (NT * 4), r = rem >> 2, c = rem & 3;
            const bf16* src = (p ? Bl : Bh) + (long long)r * ldb + kof + c * 8;
            CPA16(sb + SM_B + (s * 2 + p) * NTB + SWZ64(r * 64 + c * 16), src);
        }
        CP_COMMIT();
    };

#if HAS_TCGEN05
    if (tid == 0) { MBAR_INIT(sb + 8, 1); MBAR_INIT(sb + 16, 1); MBAR_INIT(sb + 24, 1); }
    if (wid == 0) TC_ALLOC(sb, 2 * NT);
    __syncthreads();
    uint32_t tb;
    asm volatile("ld.shared.b32 %0, [%1];" : "=r"(tb) : "r"(sb));

    constexpr uint32_t IDESC =
        (1u << 4) | (1u << 7) | (1u << 10) | ((uint32_t)(NT / 8) << 17) | (8u << 24);

    load_stage(0, 0);
    load_stage(1, 1);
    int wp[3] = {0, 0, 0};
#pragma unroll 1
    for (int c = 0; c < NC; c++) {
        int s = c % 3;
        if (c + 1 < NC) CP_WAIT1(); else CP_WAIT0();
        asm volatile("fence.proxy.async.shared::cta;" ::: "memory");
        __syncthreads();
        if (wid == 0 && elect1()) {
            uint32_t AbH = sb + SM_A + (s * 2 + 0) * 16384;
            uint32_t AbL = sb + SM_A + (s * 2 + 1) * 16384;
            uint64_t dBh = mk64(sb + SM_B + (s * 2 + 0) * NTB);
            uint64_t dBl = mk64(sb + SM_B + (s * 2 + 1) * NTB);
            uint32_t en0 = (c > 0);
#pragma unroll
            for (int m = 0; m < 2; m++) {
                uint64_t dAh = mk64(AbH + m * 8192);
                uint64_t dAl = mk64(AbL + m * 8192);
                uint32_t D = tb + m * NT;
                mma_f16_ss(D, dAh + 0, dBh + 0, IDESC, en0);
                mma_f16_ss(D, dAh + 2, dBh + 2, IDESC, 1u);
                mma_f16_ss(D, dAh + 0, dBl + 0, IDESC, 1u);
                mma_f16_ss(D, dAh + 2, dBl + 2, IDESC, 1u);
                mma_f16_ss(D, dAl + 0, dBh + 0, IDESC, 1u);
                mma_f16_ss(D, dAl + 2, dBh + 2, IDESC, 1u);
            }
            TC_COMMIT(sb + 8 + s * 8);
        }
        if (c + 2 < NC) {
            int s2 = (c + 2) % 3;
            if (c >= 1) { mbar_wait(sb + 8 + s2 * 8, wp[s2] & 1); wp[s2]++; }
            load_stage(s2, c + 2);
        }
    }
    {
        int sf = (NC - 1) % 3;
        mbar_wait(sb + 8 + sf * 8, wp[sf] & 1);
    }
    TC_FENCE_AFTER();

    {
        int m = wid >> 2;
        int lrow = m * 128 + (wid & 3) * 32 + lane;
        int grow = blockIdx.x * 256 + lrow;
        if (mode == EP_F32) {
            long long rbase = cbase + (long long)lrow * ldc;
#pragma unroll 1
            for (int cb = 0; cb < NT / 32; cb++) {
                uint32_t r[32];
                TC_LD_X32(r, tb + m * NT + cb * 32);
                TC_WAIT_LD();
                long long base = rbase + cb * 32;
#pragma unroll
                for (int j = 0; j < 32; j += 4) {
                    float4 v;
                    v.x = __uint_as_float(r[j + 0]) * alpha;
                    v.y = __uint_as_float(r[j + 1]) * alpha;
                    v.z = __uint_as_float(r[j + 2]) * alpha;
                    v.w = __uint_as_float(r[j + 3]) * alpha;
                    if (Res) {
                        float4 q = *(const float4*)(Res + base + j);
                        v.x += q.x; v.y += q.y; v.z += q.z; v.w += q.w;
                    }
                    *(float4*)(Cf + base + j) = v;
                }
            }
        } else if (mode == EP_SPLIT) {
            long long rbase = cbase + (long long)lrow * ldc;
#pragma unroll 1
            for (int cb = 0; cb < NT / 32; cb++) {
                uint32_t r[32];
                TC_LD_X32(r, tb + m * NT + cb * 32);
                TC_WAIT_LD();
                float v[32];
#pragma unroll
                for (int j = 0; j < 32; j++) v[j] = __uint_as_float(r[j]);
                split_store32(Ch + rbase + cb * 32, Cl + rbase + cb * 32, v);
            }
        } else if (mode == EP_PVNORM) {
            float inv = 1.0f / Cf[(long long)z * SS + grow];
            long long rbase = cbase + (long long)lrow * ldc;
#pragma unroll 1
            for (int cb = 0; cb < NT / 32; cb++) {
                uint32_t r[32];
                TC_LD_X32(r, tb + m * NT + cb * 32);
                TC_WAIT_LD();
                float v[32];
#pragma unroll
                for (int j = 0; j < 32; j++) v[j] = __uint_as_float(r[j]) * inv;
                split_store32(Ch + rbase + cb * 32, Cl + rbase + cb * 32, v);
            }
        } else if (mode == EP_EXP) {
            long long rbase = cbase + (long long)lrow * ldc;
            int q = grow;
            float rsum = 0.f;
#pragma unroll 1
            for (int cb = 0; cb < NT / 32; cb++) {
                uint32_t r[32];
                TC_LD_X32(r, tb + m * NT + cb * 32);
                TC_WAIT_LD();
                int col0 = blockIdx.y * NT + cb * 32;
                float v[32];
#pragma unroll
                for (int j = 0; j < 32; j++) {
                    float e = (col0 + j <= q)
                              ? __expf(__uint_as_float(r[j]) * alpha) : 0.f;
                    v[j] = e;
                    rsum += e;
                }
                split_store32(Ch + rbase + cb * 32, Cl + rbase + cb * 32, v);
            }
            atomicAdd(&Cf[(long long)z * SS + grow], rsum);
        } else if (mode == EP_SILU) {
            long long rbase = (long long)grow * (ldc >> 1) + (long long)blockIdx.y * (NT / 2);
#pragma unroll 1
            for (int cb = 0; cb < NT / 32; cb++) {
                uint32_t r[32];
                TC_LD_X32(r, tb + m * NT + cb * 32);
                TC_WAIT_LD();
                float v[16];
#pragma unroll
                for (int q = 0; q < 16; q++) {
                    float g = __uint_as_float(r[2 * q]);
                    float u = __uint_as_float(r[2 * q + 1]);
                    v[q] = g * u / (1.0f + __expf(-g));
                }
                split_store16(Ch + rbase + cb * 16, Cl + rbase + cb * 16, v);
            }
        } else {  // EP_QKV (NT == 256)
            int y = blockIdx.y;
            if (y >= 12) {
                int b = grow >> 10, scol = grow & 1023;
                long long vb = (long long)b * 1024 * 1024 + scol;
#pragma unroll 1
                for (int cb = 0; cb < 8; cb++) {
                    uint32_t r[32];
                    TC_LD_X32(r, tb + m * NT + cb * 32);
                    TC_WAIT_LD();
                    int ch0 = (y - 12) * 256 + cb * 32;
#pragma unroll
                    for (int j = 0; j < 32; j++) {
                        bf16 h, l;
                        split1(__uint_as_float(r[j]), h, l);
                        long long o = vb + (long long)(ch0 + j) * 1024;
                        Eh[o] = h; El[o] = l;
                    }
                }
            } else {
                int pos = grow & (SS - 1);
                const int pps[4] = {0, 1, 4, 5};
#pragma unroll 1
                for (int t = 0; t < 4; t++) {
                    int pp = pps[t];
                    uint32_t r1[32], r2[32];
                    TC_LD_X32(r1, tb + m * NT + pp * 32);
                    TC_LD_X32(r2, tb + m * NT + (pp + 2) * 32);
                    TC_WAIT_LD();
                    int ibase = (pp & 1) * 32;
                    int col0 = y * 256 + ((pp >> 2) << 7);
                    float v1[32], v2[32];
#pragma unroll
                    for (int j = 0; j < 32; j++) {
                        rope1(pos, ibase + j,
                              __uint_as_float(r1[j]), __uint_as_float(r2[j]),
                              v1[j], v2[j]);
                    }
                    if (y < 8) {
                        long long ob = (long long)grow * 2048 + col0 + ibase;
                        split_store32(Ch + ob, Cl + ob, v1);
                        split_store32(Ch + ob + 64, Cl + ob + 64, v2);
                    } else {
                        long long ob = (long long)grow * 1024 + (col0 - 2048) + ibase;
                        split_store32(Dh + ob, Dl + ob, v1);
                        split_store32(Dh + ob + 64, Dl + ob + 64, v2);
                    }
                }
            }
        }
    }
    __syncthreads();
    if (wid == 0) { TC_RELINQ(); TC_DEALLOC(tb, 2 * NT); }

#else
    // ------- mma.sync fallback (compute_103-legal; not selected on sm_103a) -------
    int g = lane >> 2, tg = lane & 3;
#pragma unroll 1
    for (int nh = 0; nh < NT / 128; nh++) {
        float acc[2][16][4];
#pragma unroll
        for (int g2 = 0; g2 < 2; g2++)
#pragma unroll
            for (int i = 0; i < 16; i++)
#pragma unroll
                for (int j = 0; j < 4; j++) acc[g2][i][j] = 0.f;
#pragma unroll 1
        for (int c = 0; c < NC; c++) {
            __syncthreads();
            load_stage(0, c);
            CP_WAIT0();
            __syncthreads();
#pragma unroll 1
            for (int pass = 0; pass < 3; pass++) {
                int pa = (pass == 2) ? 1 : 0;
                int pb = (pass == 1) ? 1 : 0;
                uint32_t At = sb + SM_A + pa * 16384;
                uint32_t Bt = sb + SM_B + pb * NTB;
#pragma unroll 1
                for (int g2 = 0; g2 < 2; g2++) {
                    int R = (wid * 2 + g2) * 16;
#pragma unroll
                    for (int ks = 0; ks < 2; ks++) {
                        int k0 = ks * 16;
                        uint32_t a0 = lds32(At + SWZ64((R + g) * 64 + (k0 + tg * 2) * 2));
                        uint32_t a1 = lds32(At + SWZ64((R + g + 8) * 64 + (k0 + tg * 2) * 2));
                        uint32_t a2 = lds32(At + SWZ64((R + g) * 64 + (k0 + 8 + tg * 2) * 2));
                        uint32_t a3 = lds32(At + SWZ64((R + g + 8) * 64 + (k0 + 8 + tg * 2) * 2));
#pragma unroll
                        for (int nt = 0; nt < 16; nt++) {
                            int br = nh * 128 + nt * 8 + g;
                            uint32_t b0 = lds32(Bt + SWZ64(br * 64 + (k0 + tg * 2) * 2));
                            uint32_t b1 = lds32(Bt + SWZ64(br * 64 + (k0 + 8 + tg * 2) * 2));
                            asm volatile(
                                "mma.sync.aligned.m16n8k16.row.col.f32.bf16.bf16.f32 "
                                "{%0,%1,%2,%3}, {%4,%5,%6,%7}, {%8,%9}, {%0,%1,%2,%3};"
                                : "+f"(acc[g2][nt][0]), "+f"(acc[g2][nt][1]),
                                  "+f"(acc[g2][nt][2]), "+f"(acc[g2][nt][3])
                                : "r"(a0), "r"(a1), "r"(a2), "r"(a3), "r"(b0), "r"(b1));
                        }
                    }
                }
            }
        }
#pragma unroll 1
        for (int g2 = 0; g2 < 2; g2++) {
            int R = (wid * 2 + g2) * 16;
#pragma unroll 1
            for (int rh = 0; rh < 2; rh++) {
                int lrow = R + g + rh * 8;
                int grow = blockIdx.x * 256 + lrow;
                if (mode == EP_F32) {
#pragma unroll
                    for (int nt = 0; nt < 16; nt++) {
                        int col = nh * 128 + nt * 8 + tg * 2;
                        long long o = cbase + (long long)lrow * ldc + col;
                        float a0 = acc[g2][nt][rh * 2] * alpha;
                        float a1 = acc[g2][nt][rh * 2 + 1] * alpha;
                        if (Res) { a0 += Res[o]; a1 += Res[o + 1]; }
                        Cf[o] = a0; Cf[o + 1] = a1;
                    }
                } else if (mode == EP_QKV && blockIdx.y >= 12) {
                    int b = grow >> 10, scol = grow & 1023;
                    long long vb = (long long)b * 1024 * 1024 + scol;
#pragma unroll
                    for (int nt = 0; nt < 16; nt++) {
#pragma unroll
                        for (int k = 0; k < 2; k++) {
                            int ch = (blockIdx.y - 12) * 256 + nh * 128 + nt * 8 + tg * 2 + k;
                            bf16 h, l;
                            split1(acc[g2][nt][rh * 2 + k], h, l);
                            long long o = vb + (long long)ch * 1024;
                            Eh[o] = h; El[o] = l;
                        }
                    }
                } else if (mode == EP_SPLIT || mode == EP_PVNORM) {
                    float sc = 1.0f;
                    if (mode == EP_PVNORM) sc = 1.0f / Cf[(long long)z * SS + grow];
#pragma unroll
                    for (int nt = 0; nt < 16; nt++) {
                        int col = nh * 128 + nt * 8 + tg * 2;
                        long long o = cbase + (long long)lrow * ldc + col;
                        bf16 h, l;
                        split1(acc[g2][nt][rh * 2] * sc, h, l);     Ch[o] = h;     Cl[o] = l;
                        split1(acc[g2][nt][rh * 2 + 1] * sc, h, l); Ch[o + 1] = h; Cl[o + 1] = l;
                    }
                } else if (mode == EP_EXP) {
                    int q = grow;
                    float rsum = 0.f;
#pragma unroll
                    for (int nt = 0; nt < 16; nt++) {
#pragma unroll
                        for (int k = 0; k < 2; k++) {
                            int col = blockIdx.y * NT + nh * 128 + nt * 8 + tg * 2 + k;
                            float e = (col <= q)
                                      ? __expf(acc[g2][nt][rh * 2 + k] * alpha) : 0.f;
                            long long o = cbase + (long long)lrow * ldc
                                          + nh * 128 + nt * 8 + tg * 2 + k;
                            bf16 h, l; split1(e, h, l);
                            Ch[o] = h; Cl[o] = l;
                            rsum += e;
                        }
                    }
                    atomicAdd(&Cf[(long long)z * SS + grow], rsum);
                } else if (mode == EP_SILU) {
#pragma unroll
                    for (int nt = 0; nt < 16; nt++) {
                        int col = blockIdx.y * NT + nh * 128 + nt * 8 + tg * 2;
                        float gg = acc[g2][nt][rh * 2], uu = acc[g2][nt][rh * 2 + 1];
                        float s = gg * uu / (1.0f + __expf(-gg));
                        long long o = (long long)grow * (ldc >> 1) + col / 2;
                        bf16 h, l; split1(s, h, l);
                        Ch[o] = h; Cl[o] = l;
                    }
                } else {
                    int pos = grow & (SS - 1);
#pragma unroll
                    for (int nt = 0; nt < 8; nt++) {
#pragma unroll
                        for (int k = 0; k < 2; k++) {
                            int i = nt * 8 + tg * 2 + k;
                            float x1 = acc[g2][nt][rh * 2 + k];
                            float x2 = acc[g2][nt + 8][rh * 2 + k];
                            float o1, o2;
                            rope1(pos, i, x1, x2, o1, o2);
                            int col0 = blockIdx.y * 256 + nh * 128;
                            bf16 h, l;
                            if (blockIdx.y < 8) {
                                long long ob = (long long)grow * 2048 + col0 + i;
                                split1(o1, h, l); Ch[ob] = h;      Cl[ob] = l;
                                split1(o2, h, l); Ch[ob + 64] = h; Cl[ob + 64] = l;
                            } else {
                                long long ob = (long long)grow * 1024 + (col0 - 2048) + i;
                                split1(o1, h, l); Dh[ob] = h;      Dl[ob] = l;
                                split1(o2, h, l); Dh[ob + 64] = h; Dl[ob + 64] = l;
                            }
                        }
                    }
                }
            }
        }
    }
#endif
}

// ================= elementwise kernels =================
__global__ void embed_kernel(const int* __restrict__ ids, const float* __restrict__ embed,
                             float* __restrict__ X) {
    int t = blockIdx.x;
    int id = ids[t];
    const float4* src = (const float4*)(embed + (long long)id * DD);
    float4* dst = (float4*)(X + (long long)t * DD);
    for (int i = threadIdx.x; i < DD / 4; i += blockDim.x) dst[i] = src[i];
}

__global__ void rmsnorm_split_kernel(const float* __restrict__ X, const float* __restrict__ w,
                                     bf16* __restrict__ oh, bf16* __restrict__ ol) {
    int t = blockIdx.x;
    const float* x = X + (long long)t * DD;
    float ss = 0.f;
    for (int i = threadIdx.x; i < DD; i += 256) { float v = x[i]; ss += v * v; }
    __shared__ float red[256];
    red[threadIdx.x] = ss;
    __syncthreads();
    for (int s = 128; s > 0; s >>= 1) {
        if (threadIdx.x < s) red[threadIdx.x] += red[threadIdx.x + s];
        __syncthreads();
    }
    float scale = rsqrtf(red[0] * (1.0f / DD) + 1e-6f);
    for (int i = threadIdx.x; i < DD; i += 256) {
        float v = x[i] * scale * w[i];
        bf16 h, l; split1(v, h, l);
        oh[(long long)t * DD + i] = h;
        ol[(long long)t * DD + i] = l;
    }
}

__global__ void qkvsplit_kernel(const float* __restrict__ wq, const float* __restrict__ wk,
                                const float* __restrict__ wv,
                                bf16* __restrict__ oh, bf16* __restrict__ ol) {
    long long off = ((long long)blockIdx.x * blockDim.x + threadIdx.x) * 8;
    if (off >= (long long)4096 * DD) return;
    const float* src;
    long long so;
    if (off < (long long)2048 * DD)      { src = wq; so = off; }
    else if (off < (long long)3072 * DD) { src = wk; so = off - (long long)2048 * DD; }
    else                                 { src = wv; so = off - (long long)3072 * DD; }
    float4 a = *(const float4*)(src + so);
    float4 b = *(const float4*)(src + so + 4);
    split_store8(oh + off, ol + off, a, b);
}

__global__ void gusplit_kernel(const float* __restrict__ wg, const float* __restrict__ wu,
                               bf16* __restrict__ oh, bf16* __restrict__ ol) {
    long long off = ((long long)blockIdx.x * blockDim.x + threadIdx.x) * 8;
    if (off >= (long long)16384 * DD) return;
    int orow = (int)(off >> 11);
    int col = (int)(off & 2047);
    int j = orow >> 1;
    const float* src = (orow & 1) ? wu : wg;
    long long so = (long long)j * DD + col;
    float4 a = *(const float4*)(src + so);
    float4 b = *(const float4*)(src + so + 4);
    split_store8(oh + off, ol + off, a, b);
}

__global__ void flat8split_kernel(const float* __restrict__ in,
                                  bf16* __restrict__ oh, bf16* __restrict__ ol, long long n) {
    long long off = ((long long)blockIdx.x * blockDim.x + threadIdx.x) * 8;
    if (off >= n) return;
    float4 a = *(const float4*)(in + off);
    float4 b = *(const float4*)(in + off + 4);
    split_store8(oh + off, ol + off, a, b);
}

// ================= host =================
template<int NT>
static void launch_gemm(dim3 grid,
                        const bf16* Ah, const bf16* Al, const bf16* Bh, const bf16* Bl,
                        float* Cf, bf16* Ch, bf16* Cl, bf16* Dh, bf16* Dl,
                        bf16* Eh, bf16* El,
                        const float* Res,
                        int K, int lda, int ldb, int ldc,
                        int Hdim, int hshift,
                        long long sAb, long long sAh, long long sBb, long long sBh,
                        long long sCb, long long sCh, float alpha, int causal, int mode) {
    constexpr int SMEM = 99328 + 6 * NT * 64;
    cudaFuncSetAttribute(mma_gemm_kernel<NT>, cudaFuncAttributeMaxDynamicSharedMemorySize, SMEM);
    mma_gemm_kernel<NT><<<grid, 256, SMEM>>>(Ah, Al, Bh, Bl, Cf, Ch, Cl, Dh, Dl, Eh, El, Res,
                                             K, lda, ldb, ldc, Hdim, hshift,
                                             sAb, sAh, sBb, sBh, sCb, sCh,
                                             alpha, causal, mode);
}

extern "C" void kernel_launch(void* const* d_in, const int* in_sizes, int n_in,
                              void* d_out, int out_size) {
    const int*   ids   = (const int*)d_in[0];
    const float* embed = (const float*)d_in[3];
    const float* ln1   = (const float*)d_in[4];
    const float* wq    = (const float*)d_in[5];
    const float* wk    = (const float*)d_in[6];
    const float* wv    = (const float*)d_in[7];
    const float* wo    = (const float*)d_in[8];
    const float* ln2   = (const float*)d_in[9];
    const float* wg    = (const float*)d_in[10];
    const float* wu    = (const float*)d_in[11];
    const float* wd    = (const float*)d_in[12];
    const float* nrm   = (const float*)d_in[13];
    const float* lmh   = (const float*)d_in[14];
    float* out = (float*)d_out;

    float *X, *RS;
    bf16 *XNh, *XNl, *Qh, *Ql, *Kh, *Kl, *VTh, *VTl, *Ph, *Pl, *AOh, *AOl, *Gh, *Gl;
    bf16 *Lmhh, *Lmhl;
    bf16 *Wqkvh[LL], *Wqkvl[LL], *Woh[LL], *Wol[LL], *Wguh[LL], *Wgul[LL], *Wdh[LL], *Wdl[LL];
    cudaGetSymbolAddress((void**)&X, g_X);
    cudaGetSymbolAddress((void**)&RS, g_RS);
    cudaGetSymbolAddress((void**)&XNh, g_XNh);   cudaGetSymbolAddress((void**)&XNl, g_XNl);
    cudaGetSymbolAddress((void**)&Qh, g_Qh);     cudaGetSymbolAddress((void**)&Ql, g_Ql);
    cudaGetSymbolAddress((void**)&Kh, g_Kh);     cudaGetSymbolAddress((void**)&Kl, g_Kl);
    cudaGetSymbolAddress((void**)&VTh, g_VTh);   cudaGetSymbolAddress((void**)&VTl, g_VTl);
    cudaGetSymbolAddress((void**)&Ph, g_Ph);     cudaGetSymbolAddress((void**)&Pl, g_Pl);
    cudaGetSymbolAddress((void**)&AOh, g_AOh);   cudaGetSymbolAddress((void**)&AOl, g_AOl);
    cudaGetSymbolAddress((void**)&Gh, g_Gh);     cudaGetSymbolAddress((void**)&Gl, g_Gl);
    cudaGetSymbolAddress((void**)&Lmhh, g_Lmhh); cudaGetSymbolAddress((void**)&Lmhl, g_Lmhl);
    {
        bf16 *p;
        cudaGetSymbolAddress((void**)&p, g_Wqkvh);
        for (int l = 0; l < LL; l++) Wqkvh[l] = p + (size_t)l * 4096 * DD;
        cudaGetSymbolAddress((void**)&p, g_Wqkvl);
        for (int l = 0; l < LL; l++) Wqkvl[l] = p + (size_t)l * 4096 * DD;
        cudaGetSymbolAddress((void**)&p, g_Woh);
        for (int l = 0; l < LL; l++) Woh[l] = p + (size_t)l * DD * DD;
        cudaGetSymbolAddress((void**)&p, g_Wol);
        for (int l = 0; l < LL; l++) Wol[l] = p + (size_t)l * DD * DD;
        cudaGetSymbolAddress((void**)&p, g_Wguh);
        for (int l = 0; l < LL; l++) Wguh[l] = p + (size_t)l * 16384 * DD;
        cudaGetSymbolAddress((void**)&p, g_Wgul);
        for (int l = 0; l < LL; l++) Wgul[l] = p + (size_t)l * 16384 * DD;
        cudaGetSymbolAddress((void**)&p, g_Wdh);
        for (int l = 0; l < LL; l++) Wdh[l] = p + (size_t)l * DD * FF_;
        cudaGetSymbolAddress((void**)&p, g_Wdl);
        for (int l = 0; l < LL; l++) Wdl[l] = p + (size_t)l * DD * FF_;
    }

    const float scale = 0.08838834764831845f;  // 1/sqrt(128)

    static cudaStream_t sSide = nullptr;
    static cudaEvent_t evRoot = nullptr;
    static cudaEvent_t evSplit[LL * 4 + 1];
    if (sSide == nullptr) {
        cudaStreamCreateWithFlags(&sSide, cudaStreamNonBlocking);
        cudaEventCreateWithFlags(&evRoot, cudaEventDisableTiming);
        for (int i = 0; i < LL * 4 + 1; i++)
            cudaEventCreateWithFlags(&evSplit[i], cudaEventDisableTiming);
    }

    // fork: all weight splits run on the side stream (depend only on inputs)
    cudaEventRecord(evRoot, 0);
    cudaStreamWaitEvent(sSide, evRoot, 0);
    for (int l = 0; l < LL; l++) {
        qkvsplit_kernel<<<4096, 256, 0, sSide>>>(
            wq + (long long)l * DD * DD, wk + (long long)l * KVD * DD,
            wv + (long long)l * KVD * DD, Wqkvh[l], Wqkvl[l]);
        cudaEventRecord(evSplit[l * 4 + 0], sSide);
        flat8split_kernel<<<2048, 256, 0, sSide>>>(
            wo + (long long)l * DD * DD, Woh[l], Wol[l], (long long)DD * DD);
        cudaEventRecord(evSplit[l * 4 + 1], sSide);
        gusplit_kernel<<<16384, 256, 0, sSide>>>(
            wg + (long long)l * FF_ * DD, wu + (long long)l * FF_ * DD, Wguh[l], Wgul[l]);
        cudaEventRecord(evSplit[l * 4 + 2], sSide);
        flat8split_kernel<<<8192, 256, 0, sSide>>>(
            wd + (long long)l * DD * FF_, Wdh[l], Wdl[l], (long long)DD * FF_);
        cudaEventRecord(evSplit[l * 4 + 3], sSide);
    }
    flat8split_kernel<<<32000, 256, 0, sSide>>>(lmh, Lmhh, Lmhl, (long long)VV * DD);
    cudaEventRecord(evSplit[LL * 4], sSide);

    // ---- main stream ----
    embed_kernel<<<TT, 256>>>(ids, embed, X);

    for (int l = 0; l < LL; l++) {
        rmsnorm_split_kernel<<<TT, 256>>>(X, ln1 + l * DD, XNh, XNl);

        cudaStreamWaitEvent(0, evSplit[l * 4 + 0], 0);
        // QKV GEMM: fused rope/split (Q,K) + transposed V split (VT) epilogue
        launch_gemm<256>(dim3(8, 16, 1), XNh, XNl, Wqkvh[l], Wqkvl[l],
                         nullptr, Qh, Ql, Kh, Kl, VTh, VTl, nullptr,
                         DD, DD, DD, 4096, 1, 0, 0, 0, 0, 0, 0, 0, 1.0f, 0, EP_QKV);

        cudaMemsetAsync(RS, 0, (size_t)BBX * HH * SS * sizeof(float), 0);

        // P = exp(scale * Q @ K^T) masked causal, unnormalized; rowsums -> RS
        launch_gemm<256>(dim3(4, 4, 32), Qh, Ql, Kh, Kl,
                         RS, Ph, Pl, nullptr, nullptr, nullptr, nullptr, nullptr,
                         HD, DD, KVD, SS, HH, 1,
                         (long long)SS * DD, (long long)HD,
                         (long long)SS * KVD, (long long)HD,
                         (long long)HH * SS * SS, (long long)SS * SS, scale, 1, EP_EXP);

        // AO = (P @ VT^T) / rowsum -> bf16 hi/lo directly (causal K-chunk limit)
        launch_gemm<128>(dim3(4, 1, 32), Ph, Pl, VTh, VTl,
                         RS, AOh, AOl, nullptr, nullptr, nullptr, nullptr, nullptr,
                         SS, SS, SS, DD, HH, 1,
                         (long long)HH * SS * SS, (long long)SS * SS,
                         (long long)KVH * HD * SS, (long long)HD * SS,
                         (long long)SS * DD, (long long)HD, 1.0f, 2, EP_PVNORM);

        cudaStreamWaitEvent(0, evSplit[l * 4 + 1], 0);
        // X = X + AO @ Wo^T
        launch_gemm<128>(dim3(8, 16, 1), AOh, AOl, Woh[l], Wol[l],
                         X, nullptr, nullptr, nullptr, nullptr, nullptr, nullptr, X,
                         DD, DD, DD, DD, 1, 0, 0, 0, 0, 0, 0, 0, 1.0f, 0, EP_F32);

        rmsnorm_split_kernel<<<TT, 256>>>(X, ln2 + l * DD, XNh, XNl);

        cudaStreamWaitEvent(0, evSplit[l * 4 + 2], 0);
        // G = silu(XN@Wg^T) * (XN@Wu^T) fused in epilogue
        launch_gemm<256>(dim3(8, 64, 1), XNh, XNl, Wguh[l], Wgul[l],
                         nullptr, Gh, Gl, nullptr, nullptr, nullptr, nullptr, nullptr,
                         DD, DD, DD, 16384, 1, 0, 0, 0, 0, 0, 0, 0, 1.0f, 0, EP_SILU);

        cudaStreamWaitEvent(0, evSplit[l * 4 + 3], 0);
        // X = X + G @ Wd^T
        launch_gemm<128>(dim3(8, 16, 1), Gh, Gl, Wdh[l], Wdl[l],
                         X, nullptr, nullptr, nullptr, nullptr, nullptr, nullptr, X,
                         FF_, FF_, FF_, DD, 1, 0, 0, 0, 0, 0, 0, 0, 1.0f, 0, EP_F32);
    }

    rmsnorm_split_kernel<<<TT, 256>>>(X, nrm, XNh, XNl);
    cudaStreamWaitEvent(0, evSplit[LL * 4], 0);
    // logits = XN @ lm_head^T
    launch_gemm<256>(dim3(8, 125, 1), XNh, XNl, Lmhh, Lmhl,
                     out, nullptr, nullptr, nullptr, nullptr, nullptr, nullptr, nullptr,
                     DD, DD, DD, VV, 1, 0, 0, 0, 0, 0, 0, 0, 1.0f, 0, EP_F32);
}

// round 17
// speedup vs baseline: 1.5698x; 1.0036x over previous
#include <cuda_runtime.h>
#include <cuda_bf16.h>
#include <math.h>
#include <stdint.h>

// ---------------- problem constants ----------------
#define TT   2048
#define BBX  2
#define SS   1024
#define DD   2048
#define HH   16
#define KVH  8
#define HD   128
#define KVD  1024
#define FF_  8192
#define LL   4
#define VV   32000

typedef __nv_bfloat16 bf16;

#if defined(__CUDA_ARCH_FEAT_SM103_ALL) || defined(__CUDA_ARCH_FEAT_SM100_ALL) || defined(__CUDA_ARCH_FEAT_SM101_ALL)
#define HAS_TCGEN05 1
#else
#define HAS_TCGEN05 0
#endif

// epilogue modes
#define EP_F32    0
#define EP_SILU   1
#define EP_SPLIT  2
#define EP_QKV    3
#define EP_EXP    4   // scores: e=exp(acc*alpha) masked causal; split->Ch/Cl; rowsum atomics->Cf
#define EP_PVNORM 5   // PV: acc * 1/rowsum[row] -> split Ch/Cl
// causal modes: 0 none; 1 = N-tile skip (scores); 2 = K-chunk limit per M-tile (PV)

// ---------------- scratch ----------------
__device__ __align__(256) float g_X  [TT * DD];
__device__ __align__(256) float g_RS [BBX * HH * SS];
__device__ __align__(256) float g_RS2[TT];

__device__ __align__(256) bf16 g_XNh[TT * DD],  g_XNl[TT * DD];
__device__ __align__(256) bf16 g_Qh [TT * DD],  g_Ql [TT * DD];
__device__ __align__(256) bf16 g_Kh [TT * KVD], g_Kl [TT * KVD];
__device__ __align__(256) bf16 g_VTh[TT * KVD], g_VTl[TT * KVD];
__device__ __align__(256) bf16 g_Ph [(size_t)BBX * HH * SS * SS];
__device__ __align__(256) bf16 g_Pl [(size_t)BBX * HH * SS * SS];
__device__ __align__(256) bf16 g_AOh[TT * DD],  g_AOl[TT * DD];
__device__ __align__(256) bf16 g_Gh [(size_t)TT * FF_], g_Gl[(size_t)TT * FF_];

// per-layer weight buffers (no reuse across layers -> no WAR hazard vs side stream)
__device__ __align__(256) bf16 g_Wqkvh[LL][(size_t)4096 * DD],  g_Wqkvl[LL][(size_t)4096 * DD];
__device__ __align__(256) bf16 g_Woh  [LL][(size_t)DD * DD],    g_Wol  [LL][(size_t)DD * DD];
__device__ __align__(256) bf16 g_Wguh [LL][(size_t)16384 * DD], g_Wgul [LL][(size_t)16384 * DD];
__device__ __align__(256) bf16 g_Wdh  [LL][(size_t)DD * FF_],   g_Wdl  [LL][(size_t)DD * FF_];
__device__ __align__(256) bf16 g_Lmhh [(size_t)VV * DD],        g_Lmhl [(size_t)VV * DD];

// ---------------- helpers ----------------
__device__ __forceinline__ uint32_t s2u(const void* p) {
    uint32_t a;
    asm("{ .reg .u64 t; cvta.to.shared.u64 t, %1; cvt.u32.u64 %0, t; }" : "=r"(a) : "l"(p));
    return a;
}
__device__ __forceinline__ uint32_t elect1() {
    uint32_t r;
    asm volatile("{\n\t.reg .pred p;\n\telect.sync _|p, 0xFFFFFFFF;\n\tselp.b32 %0, 1, 0, p;\n\t}" : "=r"(r));
    return r;
}
__device__ __forceinline__ uint32_t lds32(uint32_t a) {
    uint32_t v;
    asm volatile("ld.shared.b32 %0, [%1];" : "=r"(v) : "r"(a));
    return v;
}
#define SWZ64(x) ((x) ^ (((x) >> 3) & 0x30))

#define CPA16(d, s) \
    asm volatile("cp.async.cg.shared.global [%0], [%1], 16;" :: "r"(d), "l"(__cvta_generic_to_global(s)))
#define CP_COMMIT()  asm volatile("cp.async.commit_group;" ::: "memory")
#define CP_WAIT1()   asm volatile("cp.async.wait_group 1;" ::: "memory")
#define CP_WAIT0()   asm volatile("cp.async.wait_group 0;" ::: "memory")

__device__ __forceinline__ void split1(float v, bf16& h, bf16& l) {
    h = __float2bfloat16(v);
    l = __float2bfloat16(v - __bfloat162float(h));
}
__device__ __forceinline__ uint32_t packsplit(float a, float b, uint32_t& lo) {
    bf16 ha = __float2bfloat16(a), hb = __float2bfloat16(b);
    bf16 la = __float2bfloat16(a - __bfloat162float(ha));
    bf16 lb = __float2bfloat16(b - __bfloat162float(hb));
    lo = (uint32_t)*(uint16_t*)&la | ((uint32_t)*(uint16_t*)&lb << 16);
    return (uint32_t)*(uint16_t*)&ha | ((uint32_t)*(uint16_t*)&hb << 16);
}
__device__ __forceinline__ void split_store8(bf16* dh, bf16* dl, float4 a, float4 b) {
    uint32_t l0, l1, l2, l3;
    uint32_t h0 = packsplit(a.x, a.y, l0);
    uint32_t h1 = packsplit(a.z, a.w, l1);
    uint32_t h2 = packsplit(b.x, b.y, l2);
    uint32_t h3 = packsplit(b.z, b.w, l3);
    *(uint4*)dh = make_uint4(h0, h1, h2, h3);
    *(uint4*)dl = make_uint4(l0, l1, l2, l3);
}
__device__ __forceinline__ void split_store32(bf16* dh, bf16* dl, const float* v) {
    uint32_t wh[16], wl[16];
#pragma unroll
    for (int q = 0; q < 16; q++) wh[q] = packsplit(v[2*q], v[2*q+1], wl[q]);
    uint4* H = (uint4*)dh; uint4* L = (uint4*)dl;
#pragma unroll
    for (int q = 0; q < 4; q++) {
        H[q] = make_uint4(wh[4*q], wh[4*q+1], wh[4*q+2], wh[4*q+3]);
        L[q] = make_uint4(wl[4*q], wl[4*q+1], wl[4*q+2], wl[4*q+3]);
    }
}
__device__ __forceinline__ void split_store16(bf16* dh, bf16* dl, const float* v) {
    uint32_t wh[8], wl[8];
#pragma unroll
    for (int q = 0; q < 8; q++) wh[q] = packsplit(v[2*q], v[2*q+1], wl[q]);
    uint4* H = (uint4*)dh; uint4* L = (uint4*)dl;
#pragma unroll
    for (int q = 0; q < 2; q++) {
        H[q] = make_uint4(wh[4*q], wh[4*q+1], wh[4*q+2], wh[4*q+3]);
        L[q] = make_uint4(wl[4*q], wl[4*q+1], wl[4*q+2], wl[4*q+3]);
    }
}
__device__ __forceinline__ void rope1(int pos, int i, float x1, float x2, float& o1, float& o2) {
    float freq = __expf(-(float)(2 * i) * (1.0f / 128.0f) * 9.210340371976184f);
    float sn, cs;
    sincosf((float)pos * freq, &sn, &cs);
    o1 = x1 * cs - x2 * sn;
    o2 = x1 * sn + x2 * cs;
}

#if HAS_TCGEN05
constexpr uint64_t DESCBASE64 =
    (uint64_t(4) << 61) | (uint64_t(1) << 46) | (uint64_t(32) << 32) | (uint64_t(1) << 16);
__device__ __forceinline__ uint64_t mk64(uint32_t a) {
    return DESCBASE64 | ((uint64_t)(a >> 4) & 0x3FFF);
}
__device__ __forceinline__ void mma_f16_ss(uint32_t d, uint64_t ad, uint64_t bd,
                                           uint32_t idesc, uint32_t en) {
    asm volatile(
        "{\n\t.reg .pred p;\n\tsetp.ne.u32 p, %4, 0;\n\t"
        "tcgen05.mma.cta_group::1.kind::f16 [%0], %1, %2, %3, {%5,%5,%5,%5}, p;\n\t}"
        :: "r"(d), "l"(ad), "l"(bd), "r"(idesc), "r"(en), "r"(0u) : "memory");
}
#define MBAR_INIT(a, c) \
    asm volatile("mbarrier.init.shared.b64 [%0], %1;" :: "r"(a), "r"(c) : "memory")
#define TC_COMMIT(a) \
    asm volatile("tcgen05.commit.cta_group::1.mbarrier::arrive::one.shared::cluster.b64 [%0];" :: "r"(a) : "memory")
#define TC_ALLOC(sa, n) \
    asm volatile("tcgen05.alloc.cta_group::1.sync.aligned.shared::cta.b32 [%0], %1;" :: "r"(sa), "r"(n) : "memory")
#define TC_DEALLOC(t, n) \
    asm volatile("tcgen05.dealloc.cta_group::1.sync.aligned.b32 %0, %1;" :: "r"(t), "r"(n))
#define TC_RELINQ() \
    asm volatile("tcgen05.relinquish_alloc_permit.cta_group::1.sync.aligned;")
#define TC_FENCE_AFTER()  asm volatile("tcgen05.fence::after_thread_sync;" ::: "memory")
#define TC_WAIT_LD()      asm volatile("tcgen05.wait::ld.sync.aligned;" ::: "memory")

__device__ __forceinline__ void mbar_wait(uint32_t addr, uint32_t parity) {
    asm volatile(
        "{\n\t.reg .pred P;\n\t"
        "WL_%=:\n\t"
        "mbarrier.try_wait.parity.acquire.cta.shared::cta.b64 P, [%0], %1, 0x989680;\n\t"
        "@P bra.uni WD_%=;\n\t"
        "bra.uni WL_%=;\n\t"
        "WD_%=:\n\t}"
        :: "r"(addr), "r"(parity) : "memory");
}

#define TC_LD_X32(r, a) \
    asm volatile( \
        "tcgen05.ld.sync.aligned.32x32b.x32.b32 " \
        "{%0, %1, %2, %3, %4, %5, %6, %7, %8, %9, %10, %11, %12, %13, %14, %15, " \
        " %16, %17, %18, %19, %20, %21, %22, %23, %24, %25, %26, %27, %28, %29, %30, %31}, [%32];" \
        : "=r"((r)[0]), "=r"((r)[1]), "=r"((r)[2]), "=r"((r)[3]), \
          "=r"((r)[4]), "=r"((r)[5]), "=r"((r)[6]), "=r"((r)[7]), \
          "=r"((r)[8]), "=r"((r)[9]), "=r"((r)[10]), "=r"((r)[11]), \
          "=r"((r)[12]), "=r"((r)[13]), "=r"((r)[14]), "=r"((r)[15]), \
          "=r"((r)[16]), "=r"((r)[17]), "=r"((r)[18]), "=r"((r)[19]), \
          "=r"((r)[20]), "=r"((r)[21]), "=r"((r)[22]), "=r"((r)[23]), \
          "=r"((r)[24]), "=r"((r)[25]), "=r"((r)[26]), "=r"((r)[27]), \
          "=r"((r)[28]), "=r"((r)[29]), "=r"((r)[30]), "=r"((r)[31]) \
        : "r"(a))
#endif  // HAS_TCGEN05

// ======= bf16x3 GEMM: out = (A @ B^T) variants, CTA tile 256 x NT, K-chunk 32 =======
#define SM_A 1024
#define SM_B 99328   /* 1024 + 6*16384 */
template<int NT>
__global__ __launch_bounds__(256) void mma_gemm_kernel(
    const bf16* __restrict__ Ahi, const bf16* __restrict__ Alo,
    const bf16* __restrict__ Bhi, const bf16* __restrict__ Blo,
    float* __restrict__ Cf, bf16* __restrict__ Ch, bf16* __restrict__ Cl,
    bf16* __restrict__ Dh, bf16* __restrict__ Dl,
    bf16* __restrict__ Eh, bf16* __restrict__ El,
    float* __restrict__ Sq,
    const float* __restrict__ Res,
    int K, int lda, int ldb, int ldc,
    int Hdim, int hshiftB,
    long long sAb, long long sAh, long long sBb, long long sBh,
    long long sCb, long long sCh, float alpha, int causal, int mode)
{
    if (causal == 1 && (int)blockIdx.y * NT > (int)blockIdx.x * 256 + 255) return;
    extern __shared__ char smem[];
    uint32_t sb = s2u(smem);
    int tid = threadIdx.x, wid = tid >> 5, lane = tid & 31;
    int z = blockIdx.z;
    int bi = z / Hdim, hi = z - bi * Hdim;

    const bf16* Ah = Ahi + bi * sAb + hi * sAh + (long long)blockIdx.x * 256 * lda;
    const bf16* Al = Alo + bi * sAb + hi * sAh + (long long)blockIdx.x * 256 * lda;
    const bf16* Bh = Bhi + bi * sBb + (long long)(hi >> hshiftB) * sBh + (long long)blockIdx.y * NT * ldb;
    const bf16* Bl = Blo + bi * sBb + (long long)(hi >> hshiftB) * sBh + (long long)blockIdx.y * NT * ldb;
    long long cbase = bi * sCb + hi * sCh + (long long)blockIdx.x * 256 * ldc
                      + (long long)blockIdx.y * NT;

    int NC = K >> 5;
    if (causal == 2) {                      // PV: keys beyond the diagonal never needed
        int lim = ((int)blockIdx.x + 1) * 8;
        if (lim < NC) NC = lim;
    }
    constexpr int NTB = NT * 64;

    auto load_stage = [&](int s, int kc) {
        long long kof = (long long)kc * 32;
        for (int i = tid; i < 2048; i += 256) {
            int p = i >> 10, rem = i & 1023, r = rem >> 2, c = rem & 3;
            const bf16* src = (p ? Al : Ah) + (long long)r * lda + kof + c * 8;
            CPA16(sb + SM_A + (s * 2 + p) * 16384 + SWZ64(r * 64 + c * 16), src);
        }
        for (int i = tid; i < 2 * NT * 4; i += 256) {
            int p = i / (NT * 4), rem = i % (NT * 4), r = rem >> 2, c = rem & 3;
            const bf16* src = (p ? Bl : Bh) + (long long)r * ldb + kof + c * 8;
            CPA16(sb + SM_B + (s * 2 + p) * NTB + SWZ64(r * 64 + c * 16), src);
        }
        CP_COMMIT();
    };

#if HAS_TCGEN05
    if (tid == 0) { MBAR_INIT(sb + 8, 1); MBAR_INIT(sb + 16, 1); MBAR_INIT(sb + 24, 1); }
    if (wid == 0) TC_ALLOC(sb, 2 * NT);
    __syncthreads();
    uint32_t tb;
    asm volatile("ld.shared.b32 %0, [%1];" : "=r"(tb) : "r"(sb));

    constexpr uint32_t IDESC =
        (1u << 4) | (1u << 7) | (1u << 10) | ((uint32_t)(NT / 8) << 17) | (8u << 24);

    load_stage(0, 0);
    load_stage(1, 1);
    int wp[3] = {0, 0, 0};
#pragma unroll 1
    for (int c = 0; c < NC; c++) {
        int s = c % 3;
        if (c + 1 < NC) CP_WAIT1(); else CP_WAIT0();
        asm volatile("fence.proxy.async.shared::cta;" ::: "memory");
        __syncthreads();
        if (wid == 0 && elect1()) {
            uint32_t AbH = sb + SM_A + (s * 2 + 0) * 16384;
            uint32_t AbL = sb + SM_A + (s * 2 + 1) * 16384;
            uint64_t dBh = mk64(sb + SM_B + (s * 2 + 0) * NTB);
            uint64_t dBl = mk64(sb + SM_B + (s * 2 + 1) * NTB);
            uint32_t en0 = (c > 0);
#pragma unroll
            for (int m = 0; m < 2; m++) {
                uint64_t dAh = mk64(AbH + m * 8192);
                uint64_t dAl = mk64(AbL + m * 8192);
                uint32_t D = tb + m * NT;
                mma_f16_ss(D, dAh + 0, dBh + 0, IDESC, en0);
                mma_f16_ss(D, dAh + 2, dBh + 2, IDESC, 1u);
                mma_f16_ss(D, dAh + 0, dBl + 0, IDESC, 1u);
                mma_f16_ss(D, dAh + 2, dBl + 2, IDESC, 1u);
                mma_f16_ss(D, dAl + 0, dBh + 0, IDESC, 1u);
                mma_f16_ss(D, dAl + 2, dBh + 2, IDESC, 1u);
            }
            TC_COMMIT(sb + 8 + s * 8);
        }
        if (c + 2 < NC) {
            int s2 = (c + 2) % 3;
            if (c >= 1) { mbar_wait(sb + 8 + s2 * 8, wp[s2] & 1); wp[s2]++; }
            load_stage(s2, c + 2);
        }
    }
    {
        int sf = (NC - 1) % 3;
        mbar_wait(sb + 8 + sf * 8, wp[sf] & 1);
    }
    TC_FENCE_AFTER();

    {
        int m = wid >> 5; // placeholder (recomputed below)
        m = wid >> 2;
        int lrow = m * 128 + (wid & 3) * 32 + lane;
        int grow = blockIdx.x * 256 + lrow;
        if (mode == EP_F32) {
            long long rbase = cbase + (long long)lrow * ldc;
            float sq = 0.f;
#pragma unroll 1
            for (int cb = 0; cb < NT / 32; cb++) {
                uint32_t r[32];
                TC_LD_X32(r, tb + m * NT + cb * 32);
                TC_WAIT_LD();
                long long base = rbase + cb * 32;
#pragma unroll
                for (int j = 0; j < 32; j += 4) {
                    float4 v;
                    v.x = __uint_as_float(r[j + 0]) * alpha;
                    v.y = __uint_as_float(r[j + 1]) * alpha;
                    v.z = __uint_as_float(r[j + 2]) * alpha;
                    v.w = __uint_as_float(r[j + 3]) * alpha;
                    if (Res) {
                        float4 q = *(const float4*)(Res + base + j);
                        v.x += q.x; v.y += q.y; v.z += q.z; v.w += q.w;
                    }
                    if (Sq) sq += v.x * v.x + v.y * v.y + v.z * v.z + v.w * v.w;
                    *(float4*)(Cf + base + j) = v;
                }
            }
            if (Sq) atomicAdd(&Sq[grow], sq);
        } else if (mode == EP_SPLIT) {
            long long rbase = cbase + (long long)lrow * ldc;
#pragma unroll 1
            for (int cb = 0; cb < NT / 32; cb++) {
                uint32_t r[32];
                TC_LD_X32(r, tb + m * NT + cb * 32);
                TC_WAIT_LD();
                float v[32];
#pragma unroll
                for (int j = 0; j < 32; j++) v[j] = __uint_as_float(r[j]);
                split_store32(Ch + rbase + cb * 32, Cl + rbase + cb * 32, v);
            }
        } else if (mode == EP_PVNORM) {
            float inv = 1.0f / Cf[(long long)z * SS + grow];
            long long rbase = cbase + (long long)lrow * ldc;
#pragma unroll 1
            for (int cb = 0; cb < NT / 32; cb++) {
                uint32_t r[32];
                TC_LD_X32(r, tb + m * NT + cb * 32);
                TC_WAIT_LD();
                float v[32];
#pragma unroll
                for (int j = 0; j < 32; j++) v[j] = __uint_as_float(r[j]) * inv;
                split_store32(Ch + rbase + cb * 32, Cl + rbase + cb * 32, v);
            }
        } else if (mode == EP_EXP) {
            long long rbase = cbase + (long long)lrow * ldc;
            int q = grow;
            float rsum = 0.f;
#pragma unroll 1
            for (int cb = 0; cb < NT / 32; cb++) {
                uint32_t r[32];
                TC_LD_X32(r, tb + m * NT + cb * 32);
                TC_WAIT_LD();
                int col0 = blockIdx.y * NT + cb * 32;
                float v[32];
#pragma unroll
                for (int j = 0; j < 32; j++) {
                    float e = (col0 + j <= q)
                              ? __expf(__uint_as_float(r[j]) * alpha) : 0.f;
                    v[j] = e;
                    rsum += e;
                }
                split_store32(Ch + rbase + cb * 32, Cl + rbase + cb * 32, v);
            }
            atomicAdd(&Cf[(long long)z * SS + grow], rsum);
        } else if (mode == EP_SILU) {
            long long rbase = (long long)grow * (ldc >> 1) + (long long)blockIdx.y * (NT / 2);
#pragma unroll 1
            for (int cb = 0; cb < NT / 32; cb++) {
                uint32_t r[32];
                TC_LD_X32(r, tb + m * NT + cb * 32);
                TC_WAIT_LD();
                float v[16];
#pragma unroll
                for (int q = 0; q < 16; q++) {
                    float g = __uint_as_float(r[2 * q]);
                    float u = __uint_as_float(r[2 * q + 1]);
                    v[q] = g * u / (1.0f + __expf(-g));
                }
                split_store16(Ch + rbase + cb * 16, Cl + rbase + cb * 16, v);
            }
        } else {  // EP_QKV (NT == 256)
            int y = blockIdx.y;
            if (y >= 12) {
                int b = grow >> 10, scol = grow & 1023;
                long long vb = (long long)b * 1024 * 1024 + scol;
#pragma unroll 1
                for (int cb = 0; cb < 8; cb++) {
                    uint32_t r[32];
                    TC_LD_X32(r, tb + m * NT + cb * 32);
                    TC_WAIT_LD();
                    int ch0 = (y - 12) * 256 + cb * 32;
#pragma unroll
                    for (int j = 0; j < 32; j++) {
                        bf16 h, l;
                        split1(__uint_as_float(r[j]), h, l);
                        long long o = vb + (long long)(ch0 + j) * 1024;
                        Eh[o] = h; El[o] = l;
                    }
                }
            } else {
                int pos = grow & (SS - 1);
                const int pps[4] = {0, 1, 4, 5};
#pragma unroll 1
                for (int t = 0; t < 4; t++) {
                    int pp = pps[t];
                    uint32_t r1[32], r2[32];
                    TC_LD_X32(r1, tb + m * NT + pp * 32);
                    TC_LD_X32(r2, tb + m * NT + (pp + 2) * 32);
                    TC_WAIT_LD();
                    int ibase = (pp & 1) * 32;
                    int col0 = y * 256 + ((pp >> 2) << 7);
                    float v1[32], v2[32];
#pragma unroll
                    for (int j = 0; j < 32; j++) {
                        rope1(pos, ibase + j,
                              __uint_as_float(r1[j]), __uint_as_float(r2[j]),
                              v1[j], v2[j]);
                    }
                    if (y < 8) {
                        long long ob = (long long)grow * 2048 + col0 + ibase;
                        split_store32(Ch + ob, Cl + ob, v1);
                        split_store32(Ch + ob + 64, Cl + ob + 64, v2);
                    } else {
                        long long ob = (long long)grow * 1024 + (col0 - 2048) + ibase;
                        split_store32(Dh + ob, Dl + ob, v1);
                        split_store32(Dh + ob + 64, Dl + ob + 64, v2);
                    }
                }
            }
        }
    }
    __syncthreads();
    if (wid == 0) { TC_RELINQ(); TC_DEALLOC(tb, 2 * NT); }

#else
    // ------- mma.sync fallback (compute_103-legal; not selected on sm_103a) -------
    int g = lane >> 2, tg = lane & 3;
#pragma unroll 1
    for (int nh = 0; nh < NT / 128; nh++) {
        float acc[2][16][4];
#pragma unroll
        for (int g2 = 0; g2 < 2; g2++)
#pragma unroll
            for (int i = 0; i < 16; i++)
#pragma unroll
                for (int j = 0; j < 4; j++) acc[g2][i][j] = 0.f;
#pragma unroll 1
        for (int c = 0; c < NC; c++) {
            __syncthreads();
            load_stage(0, c);
            CP_WAIT0();
            __syncthreads();
#pragma unroll 1
            for (int pass = 0; pass < 3; pass++) {
                int pa = (pass == 2) ? 1 : 0;
                int pb = (pass == 1) ? 1 : 0;
                uint32_t At = sb + SM_A + pa * 16384;
                uint32_t Bt = sb + SM_B + pb * NTB;
#pragma unroll 1
                for (int g2 = 0; g2 < 2; g2++) {
                    int R = (wid * 2 + g2) * 16;
#pragma unroll
                    for (int ks = 0; ks < 2; ks++) {
                        int k0 = ks * 16;
                        uint32_t a0 = lds32(At + SWZ64((R + g) * 64 + (k0 + tg * 2) * 2));
                        uint32_t a1 = lds32(At + SWZ64((R + g + 8) * 64 + (k0 + tg * 2) * 2));
                        uint32_t a2 = lds32(At + SWZ64((R + g) * 64 + (k0 + 8 + tg * 2) * 2));
                        uint32_t a3 = lds32(At + SWZ64((R + g + 8) * 64 + (k0 + 8 + tg * 2) * 2));
#pragma unroll
                        for (int nt = 0; nt < 16; nt++) {
                            int br = nh * 128 + nt * 8 + g;
                            uint32_t b0 = lds32(Bt + SWZ64(br * 64 + (k0 + tg * 2) * 2));
                            uint32_t b1 = lds32(Bt + SWZ64(br * 64 + (k0 + 8 + tg * 2) * 2));
                            asm volatile(
                                "mma.sync.aligned.m16n8k16.row.col.f32.bf16.bf16.f32 "
                                "{%0,%1,%2,%3}, {%4,%5,%6,%7}, {%8,%9}, {%0,%1,%2,%3};"
                                : "+f"(acc[g2][nt][0]), "+f"(acc[g2][nt][1]),
                                  "+f"(acc[g2][nt][2]), "+f"(acc[g2][nt][3])
                                : "r"(a0), "r"(a1), "r"(a2), "r"(a3), "r"(b0), "r"(b1));
                        }
                    }
                }
            }
        }
#pragma unroll 1
        for (int g2 = 0; g2 < 2; g2++) {
            int R = (wid * 2 + g2) * 16;
#pragma unroll 1
            for (int rh = 0; rh < 2; rh++) {
                int lrow = R + g + rh * 8;
                int grow = blockIdx.x * 256 + lrow;
                if (mode == EP_F32) {
                    float sq = 0.f;
#pragma unroll
                    for (int nt = 0; nt < 16; nt++) {
                        int col = nh * 128 + nt * 8 + tg * 2;
                        long long o = cbase + (long long)lrow * ldc + col;
                        float a0 = acc[g2][nt][rh * 2] * alpha;
                        float a1 = acc[g2][nt][rh * 2 + 1] * alpha;
                        if (Res) { a0 += Res[o]; a1 += Res[o + 1]; }
                        if (Sq) sq += a0 * a0 + a1 * a1;
                        Cf[o] = a0; Cf[o + 1] = a1;
                    }
                    if (Sq) atomicAdd(&Sq[grow], sq);
                } else if (mode == EP_QKV && blockIdx.y >= 12) {
                    int b = grow >> 10, scol = grow & 1023;
                    long long vb = (long long)b * 1024 * 1024 + scol;
#pragma unroll
                    for (int nt = 0; nt < 16; nt++) {
#pragma unroll
                        for (int k = 0; k < 2; k++) {
                            int ch = (blockIdx.y - 12) * 256 + nh * 128 + nt * 8 + tg * 2 + k;
                            bf16 h, l;
                            split1(acc[g2][nt][rh * 2 + k], h, l);
                            long long o = vb + (long long)ch * 1024;
                            Eh[o] = h; El[o] = l;
                        }
                    }
                } else if (mode == EP_SPLIT || mode == EP_PVNORM) {
                    float sc = 1.0f;
                    if (mode == EP_PVNORM) sc = 1.0f / Cf[(long long)z * SS + grow];
#pragma unroll
                    for (int nt = 0; nt < 16; nt++) {
                        int col = nh * 128 + nt * 8 + tg * 2;
                        long long o = cbase + (long long)lrow * ldc + col;
                        bf16 h, l;
                        split1(acc[g2][nt][rh * 2] * sc, h, l);     Ch[o] = h;     Cl[o] = l;
                        split1(acc[g2][nt][rh * 2 + 1] * sc, h, l); Ch[o + 1] = h; Cl[o + 1] = l;
                    }
                } else if (mode == EP_EXP) {
                    int q = grow;
                    float rsum = 0.f;
#pragma unroll
                    for (int nt = 0; nt < 16; nt++) {
#pragma unroll
                        for (int k = 0; k < 2; k++) {
                            int col = blockIdx.y * NT + nh * 128 + nt * 8 + tg * 2 + k;
                            float e = (col <= q)
                                      ? __expf(acc[g2][nt][rh * 2 + k] * alpha) : 0.f;
                            long long o = cbase + (long long)lrow * ldc
                                          + nh * 128 + nt * 8 + tg * 2 + k;
                            bf16 h, l; split1(e, h, l);
                            Ch[o] = h; Cl[o] = l;
                            rsum += e;
                        }
                    }
                    atomicAdd(&Cf[(long long)z * SS + grow], rsum);
                } else if (mode == EP_SILU) {
#pragma unroll
                    for (int nt = 0; nt < 16; nt++) {
                        int col = blockIdx.y * NT + nh * 128 + nt * 8 + tg * 2;
                        float gg = acc[g2][nt][rh * 2], uu = acc[g2][nt][rh * 2 + 1];
                        float s = gg * uu / (1.0f + __expf(-gg));
                        long long o = (long long)grow * (ldc >> 1) + col / 2;
                        bf16 h, l; split1(s, h, l);
                        Ch[o] = h; Cl[o] = l;
                    }
                } else {
                    int pos = grow & (SS - 1);
#pragma unroll
                    for (int nt = 0; nt < 8; nt++) {
#pragma unroll
                        for (int k = 0; k < 2; k++) {
                            int i = nt * 8 + tg * 2 + k;
                            float x1 = acc[g2][nt][rh * 2 + k];
                            float x2 = acc[g2][nt + 8][rh * 2 + k];
                            float o1, o2;
                            rope1(pos, i, x1, x2, o1, o2);
                            int col0 = blockIdx.y * 256 + nh * 128;
                            bf16 h, l;
                            if (blockIdx.y < 8) {
                                long long ob = (long long)grow * 2048 + col0 + i;
                                split1(o1, h, l); Ch[ob] = h;      Cl[ob] = l;
                                split1(o2, h, l); Ch[ob + 64] = h; Cl[ob + 64] = l;
                            } else {
                                long long ob = (long long)grow * 1024 + (col0 - 2048) + i;
                                split1(o1, h, l); Dh[ob] = h;      Dl[ob] = l;
                                split1(o2, h, l); Dh[ob + 64] = h; Dl[ob + 64] = l;
                            }
                        }
                    }
                }
            }
        }
    }
#endif
}

// ================= elementwise kernels =================
// embed + full-row sum of squares -> RS2[t]
__global__ void embed_kernel(const int* __restrict__ ids, const float* __restrict__ embed,
                             float* __restrict__ X, float* __restrict__ RS2) {
    __shared__ float red[256];
    int t = blockIdx.x;
    int id = ids[t];
    const float4* src = (const float4*)(embed + (long long)id * DD);
    float4* dst = (float4*)(X + (long long)t * DD);
    float ss = 0.f;
    for (int i = threadIdx.x; i < DD / 4; i += blockDim.x) {
        float4 v = src[i];
        dst[i] = v;
        ss += v.x * v.x + v.y * v.y + v.z * v.z + v.w * v.w;
    }
    red[threadIdx.x] = ss;
    __syncthreads();
    for (int s = 128; s > 0; s >>= 1) {
        if (threadIdx.x < s) red[threadIdx.x] += red[threadIdx.x + s];
        __syncthreads();
    }
    if (threadIdx.x == 0) RS2[t] = red[0];
}

// single-pass rmsnorm: row sumsq precomputed in RS2
__global__ void rmsnorm_split_kernel(const float* __restrict__ X, const float* __restrict__ w,
                                     const float* __restrict__ RS2,
                                     bf16* __restrict__ oh, bf16* __restrict__ ol) {
    int t = blockIdx.x;
    const float* x = X + (long long)t * DD;
    float scale = rsqrtf(RS2[t] * (1.0f / DD) + 1e-6f);
    for (int i = threadIdx.x * 2; i < DD; i += 512) {
        float a = x[i] * scale * w[i];
        float b = x[i + 1] * scale * w[i + 1];
        uint32_t lo;
        uint32_t hi = packsplit(a, b, lo);
        *(uint32_t*)(oh + (long long)t * DD + i) = hi;
        *(uint32_t*)(ol + (long long)t * DD + i) = lo;
    }
}

__global__ void qkvsplit_kernel(const float* __restrict__ wq, const float* __restrict__ wk,
                                const float* __restrict__ wv,
                                bf16* __restrict__ oh, bf16* __restrict__ ol) {
    long long off = ((long long)blockIdx.x * blockDim.x + threadIdx.x) * 8;
    if (off >= (long long)4096 * DD) return;
    const float* src;
    long long so;
    if (off < (long long)2048 * DD)      { src = wq; so = off; }
    else if (off < (long long)3072 * DD) { src = wk; so = off - (long long)2048 * DD; }
    else                                 { src = wv; so = off - (long long)3072 * DD; }
    float4 a = *(const float4*)(src + so);
    float4 b = *(const float4*)(src + so + 4);
    split_store8(oh + off, ol + off, a, b);
}

__global__ void gusplit_kernel(const float* __restrict__ wg, const float* __restrict__ wu,
                               bf16* __restrict__ oh, bf16* __restrict__ ol) {
    long long off = ((long long)blockIdx.x * blockDim.x + threadIdx.x) * 8;
    if (off >= (long long)16384 * DD) return;
    int orow = (int)(off >> 11);
    int col = (int)(off & 2047);
    int j = orow >> 1;
    const float* src = (orow & 1) ? wu : wg;
    long long so = (long long)j * DD + col;
    float4 a = *(const float4*)(src + so);
    float4 b = *(const float4*)(src + so + 4);
    split_store8(oh + off, ol + off, a, b);
}

__global__ void flat8split_kernel(const float* __restrict__ in,
                                  bf16* __restrict__ oh, bf16* __restrict__ ol, long long n) {
    long long off = ((long long)blockIdx.x * blockDim.x + threadIdx.x) * 8;
    if (off >= n) return;
    float4 a = *(const float4*)(in + off);
    float4 b = *(const float4*)(in + off + 4);
    split_store8(oh + off, ol + off, a, b);
}

// ================= host =================
template<int NT>
static void launch_gemm(dim3 grid,
                        const bf16* Ah, const bf16* Al, const bf16* Bh, const bf16* Bl,
                        float* Cf, bf16* Ch, bf16* Cl, bf16* Dh, bf16* Dl,
                        bf16* Eh, bf16* El, float* Sq,
                        const float* Res,
                        int K, int lda, int ldb, int ldc,
                        int Hdim, int hshift,
                        long long sAb, long long sAh, long long sBb, long long sBh,
                        long long sCb, long long sCh, float alpha, int causal, int mode) {
    constexpr int SMEM = 99328 + 6 * NT * 64;
    cudaFuncSetAttribute(mma_gemm_kernel<NT>, cudaFuncAttributeMaxDynamicSharedMemorySize, SMEM);
    mma_gemm_kernel<NT><<<grid, 256, SMEM>>>(Ah, Al, Bh, Bl, Cf, Ch, Cl, Dh, Dl, Eh, El, Sq,
                                             Res, K, lda, ldb, ldc, Hdim, hshift,
                                             sAb, sAh, sBb, sBh, sCb, sCh,
                                             alpha, causal, mode);
}

extern "C" void kernel_launch(void* const* d_in, const int* in_sizes, int n_in,
                              void* d_out, int out_size) {
    const int*   ids   = (const int*)d_in[0];
    const float* embed = (const float*)d_in[3];
    const float* ln1   = (const float*)d_in[4];
    const float* wq    = (const float*)d_in[5];
    const float* wk    = (const float*)d_in[6];
    const float* wv    = (const float*)d_in[7];
    const float* wo    = (const float*)d_in[8];
    const float* ln2   = (const float*)d_in[9];
    const float* wg    = (const float*)d_in[10];
    const float* wu    = (const float*)d_in[11];
    const float* wd    = (const float*)d_in[12];
    const float* nrm   = (const float*)d_in[13];
    const float* lmh   = (const float*)d_in[14];
    float* out = (float*)d_out;

    float *X, *RS, *RS2;
    bf16 *XNh, *XNl, *Qh, *Ql, *Kh, *Kl, *VTh, *VTl, *Ph, *Pl, *AOh, *AOl, *Gh, *Gl;
    bf16 *Lmhh, *Lmhl;
    bf16 *Wqkvh[LL], *Wqkvl[LL], *Woh[LL], *Wol[LL], *Wguh[LL], *Wgul[LL], *Wdh[LL], *Wdl[LL];
    cudaGetSymbolAddress((void**)&X, g_X);
    cudaGetSymbolAddress((void**)&RS, g_RS);
    cudaGetSymbolAddress((void**)&RS2, g_RS2);
    cudaGetSymbolAddress((void**)&XNh, g_XNh);   cudaGetSymbolAddress((void**)&XNl, g_XNl);
    cudaGetSymbolAddress((void**)&Qh, g_Qh);     cudaGetSymbolAddress((void**)&Ql, g_Ql);
    cudaGetSymbolAddress((void**)&Kh, g_Kh);     cudaGetSymbolAddress((void**)&Kl, g_Kl);
    cudaGetSymbolAddress((void**)&VTh, g_VTh);   cudaGetSymbolAddress((void**)&VTl, g_VTl);
    cudaGetSymbolAddress((void**)&Ph, g_Ph);     cudaGetSymbolAddress((void**)&Pl, g_Pl);
    cudaGetSymbolAddress((void**)&AOh, g_AOh);   cudaGetSymbolAddress((void**)&AOl, g_AOl);
    cudaGetSymbolAddress((void**)&Gh, g_Gh);     cudaGetSymbolAddress((void**)&Gl, g_Gl);
    cudaGetSymbolAddress((void**)&Lmhh, g_Lmhh); cudaGetSymbolAddress((void**)&Lmhl, g_Lmhl);
    {
        bf16 *p;
        cudaGetSymbolAddress((void**)&p, g_Wqkvh);
        for (int l = 0; l < LL; l++) Wqkvh[l] = p + (size_t)l * 4096 * DD;
        cudaGetSymbolAddress((void**)&p, g_Wqkvl);
        for (int l = 0; l < LL; l++) Wqkvl[l] = p + (size_t)l * 4096 * DD;
        cudaGetSymbolAddress((void**)&p, g_Woh);
        for (int l = 0; l < LL; l++) Woh[l] = p + (size_t)l * DD * DD;
        cudaGetSymbolAddress((void**)&p, g_Wol);
        for (int l = 0; l < LL; l++) Wol[l] = p + (size_t)l * DD * DD;
        cudaGetSymbolAddress((void**)&p, g_Wguh);
        for (int l = 0; l < LL; l++) Wguh[l] = p + (size_t)l * 16384 * DD;
        cudaGetSymbolAddress((void**)&p, g_Wgul);
        for (int l = 0; l < LL; l++) Wgul[l] = p + (size_t)l * 16384 * DD;
        cudaGetSymbolAddress((void**)&p, g_Wdh);
        for (int l = 0; l < LL; l++) Wdh[l] = p + (size_t)l * DD * FF_;
        cudaGetSymbolAddress((void**)&p, g_Wdl);
        for (int l = 0; l < LL; l++) Wdl[l] = p + (size_t)l * DD * FF_;
    }

    const float scale = 0.08838834764831845f;  // 1/sqrt(128)

    static cudaStream_t sSide = nullptr;
    static cudaEvent_t evRoot = nullptr;
    static cudaEvent_t evSplit[LL * 4 + 1];
    if (sSide == nullptr) {
        cudaStreamCreateWithFlags(&sSide, cudaStreamNonBlocking);
        cudaEventCreateWithFlags(&evRoot, cudaEventDisableTiming);
        for (int i = 0; i < LL * 4 + 1; i++)
            cudaEventCreateWithFlags(&evSplit[i], cudaEventDisableTiming);
    }

    // fork: all weight splits run on the side stream (depend only on inputs)
    cudaEventRecord(evRoot, 0);
    cudaStreamWaitEvent(sSide, evRoot, 0);
    for (int l = 0; l < LL; l++) {
        qkvsplit_kernel<<<4096, 256, 0, sSide>>>(
            wq + (long long)l * DD * DD, wk + (long long)l * KVD * DD,
            wv + (long long)l * KVD * DD, Wqkvh[l], Wqkvl[l]);
        cudaEventRecord(evSplit[l * 4 + 0], sSide);
        flat8split_kernel<<<2048, 256, 0, sSide>>>(
            wo + (long long)l * DD * DD, Woh[l], Wol[l], (long long)DD * DD);
        cudaEventRecord(evSplit[l * 4 + 1], sSide);
        gusplit_kernel<<<16384, 256, 0, sSide>>>(
            wg + (long long)l * FF_ * DD, wu + (long long)l * FF_ * DD, Wguh[l], Wgul[l]);
        cudaEventRecord(evSplit[l * 4 + 2], sSide);
        flat8split_kernel<<<8192, 256, 0, sSide>>>(
            wd + (long long)l * DD * FF_, Wdh[l], Wdl[l], (long long)DD * FF_);
        cudaEventRecord(evSplit[l * 4 + 3], sSide);
    }
    flat8split_kernel<<<32000, 256, 0, sSide>>>(lmh, Lmhh, Lmhl, (long long)VV * DD);
    cudaEventRecord(evSplit[LL * 4], sSide);

    // ---- main stream ----
    embed_kernel<<<TT, 256>>>(ids, embed, X, RS2);

    for (int l = 0; l < LL; l++) {
        // rmsnorm1: RS2 produced by embed (l=0) or previous Wd epilogue
        rmsnorm_split_kernel<<<TT, 256>>>(X, ln1 + l * DD, RS2, XNh, XNl);

        cudaStreamWaitEvent(0, evSplit[l * 4 + 0], 0);
        // QKV GEMM: fused rope/split (Q,K) + transposed V split (VT) epilogue
        launch_gemm<256>(dim3(8, 16, 1), XNh, XNl, Wqkvh[l], Wqkvl[l],
                         nullptr, Qh, Ql, Kh, Kl, VTh, VTl, nullptr, nullptr,
                         DD, DD, DD, 4096, 1, 0, 0, 0, 0, 0, 0, 0, 1.0f, 0, EP_QKV);

        cudaMemsetAsync(RS, 0, (size_t)BBX * HH * SS * sizeof(float), 0);

        // P = exp(scale * Q @ K^T) masked causal, unnormalized; rowsums -> RS
        launch_gemm<256>(dim3(4, 4, 32), Qh, Ql, Kh, Kl,
                         RS, Ph, Pl, nullptr, nullptr, nullptr, nullptr, nullptr, nullptr,
                         HD, DD, KVD, SS, HH, 1,
                         (long long)SS * DD, (long long)HD,
                         (long long)SS * KVD, (long long)HD,
                         (long long)HH * SS * SS, (long long)SS * SS, scale, 1, EP_EXP);

        // AO = (P @ VT^T) / rowsum -> bf16 hi/lo directly (causal K-chunk limit)
        launch_gemm<128>(dim3(4, 1, 32), Ph, Pl, VTh, VTl,
                         RS, AOh, AOl, nullptr, nullptr, nullptr, nullptr, nullptr, nullptr,
                         SS, SS, SS, DD, HH, 1,
                         (long long)HH * SS * SS, (long long)SS * SS,
                         (long long)KVH * HD * SS, (long long)HD * SS,
                         (long long)SS * DD, (long long)HD, 1.0f, 2, EP_PVNORM);

        cudaMemsetAsync(RS2, 0, (size_t)TT * sizeof(float), 0);
        cudaStreamWaitEvent(0, evSplit[l * 4 + 1], 0);
        // X = X + AO @ Wo^T; row sumsq -> RS2
        launch_gemm<128>(dim3(8, 16, 1), AOh, AOl, Woh[l], Wol[l],
                         X, nullptr, nullptr, nullptr, nullptr, nullptr, nullptr, RS2, X,
                         DD, DD, DD, DD, 1, 0, 0, 0, 0, 0, 0, 0, 1.0f, 0, EP_F32);

        rmsnorm_split_kernel<<<TT, 256>>>(X, ln2 + l * DD, RS2, XNh, XNl);

        cudaStreamWaitEvent(0, evSplit[l * 4 + 2], 0);
        // G = silu(XN@Wg^T) * (XN@Wu^T) fused in epilogue
        launch_gemm<256>(dim3(8, 64, 1), XNh, XNl, Wguh[l], Wgul[l],
                         nullptr, Gh, Gl, nullptr, nullptr, nullptr, nullptr, nullptr, nullptr,
                         DD, DD, DD, 16384, 1, 0, 0, 0, 0, 0, 0, 0, 1.0f, 0, EP_SILU);

        cudaMemsetAsync(RS2, 0, (size_t)TT * sizeof(float), 0);
        cudaStreamWaitEvent(0, evSplit[l * 4 + 3], 0);
        // X = X + G @ Wd^T; row sumsq -> RS2 (feeds next rmsnorm)
        launch_gemm<128>(dim3(8, 16, 1), Gh, Gl, Wdh[l], Wdl[l],
                         X, nullptr, nullptr, nullptr, nullptr, nullptr, nullptr, RS2, X,
                         FF_, FF_, FF_, DD, 1, 0, 0, 0, 0, 0, 0, 0, 1.0f, 0, EP_F32);
    }

    rmsnorm_split_kernel<<<TT, 256>>>(X, nrm, RS2, XNh, XNl);
    cudaStreamWaitEvent(0, evSplit[LL * 4], 0);
    // logits = XN @ lm_head^T
    launch_gemm<256>(dim3(8, 125, 1), XNh, XNl, Lmhh, Lmhl,
                     out, nullptr, nullptr, nullptr, nullptr, nullptr, nullptr, nullptr, nullptr,
                     DD, DD, DD, VV, 1, 0, 0, 0, 0, 0, 0, 0, 1.0f, 0, EP_F32);
}